// round 5
// baseline (speedup 1.0000x reference)
#include <cuda_runtime.h>

#define NMAX 50000
#define EMAX 800000
#define LN_EPS 1e-5f

// ---------------- scratch (device globals; no allocation allowed) ----------------
__device__ __align__(16) int   g_srcdeg[NMAX];
__device__ __align__(16) int   g_rowcnt[NMAX];
__device__ __align__(16) int   g_rowptr[NMAX + 1];
__device__ __align__(16) int   g_eoff[EMAX];             // per-edge intra-row offset
__device__ __align__(16) float g_dinv[NMAX];
__device__ __align__(16) int2  g_csr[EMAX];              // {src, bitcast(w)} grouped by dst
__device__ __align__(16) float g_H [NMAX * 64];
__device__ __align__(16) float g_T1[NMAX * 64];
__device__ __align__(16) float g_U1[NMAX * 64];          // T1 @ A1
__device__ __align__(16) float g_U2[NMAX * 64];          // (L@T1) @ A2
__device__ __align__(16) float g_A [3 * 3 * 64 * 64];    // folded weights

// ---------------- f32x2 packed-FMA helpers ----------------
__device__ __forceinline__ unsigned long long pack2(float a, float b) {
    unsigned long long r;
    asm("mov.b64 %0, {%1, %2};" : "=l"(r) : "f"(a), "f"(b));
    return r;
}
__device__ __forceinline__ unsigned long long ffma2(unsigned long long a,
                                                    unsigned long long b,
                                                    unsigned long long c) {
    unsigned long long d;
    asm("fma.rn.f32x2 %0, %1, %2, %3;" : "=l"(d) : "l"(a), "l"(b), "l"(c));
    return d;
}
__device__ __forceinline__ float2 unpack2(unsigned long long v) {
    float2 f;
    asm("mov.b64 {%0, %1}, %2;" : "=f"(f.x), "=f"(f.y) : "l"(v));
    return f;
}

// ---------------- weight folding: A0 = W0 - W2, A1 = W1, A2 = 2*W2 ----------------
__global__ void prepA_kernel(const float* __restrict__ W) {
    int idx = blockIdx.x * blockDim.x + threadIdx.x;
    if (idx < 3 * 4096) {
        int i = idx >> 12, r = idx & 4095;
        const float* Wi = W + i * 3 * 4096;
        float w0 = Wi[r], w1 = Wi[4096 + r], w2 = Wi[8192 + r];
        float* Ai = g_A + i * 3 * 4096;
        Ai[r]        = w0 - w2;
        Ai[4096 + r] = w1;
        Ai[8192 + r] = 2.0f * w2;
    }
}

__global__ void zero_kernel(int n) {
    int i = blockIdx.x * blockDim.x + threadIdx.x;
    if (i < n) { g_srcdeg[i] = 0; g_rowcnt[i] = 0; }
}

// scalar, 1 edge/thread (proven fastest); atomic return value = intra-row slot
__global__ void count_kernel(const int* __restrict__ src, const int* __restrict__ dst, int e) {
    int i = blockIdx.x * blockDim.x + threadIdx.x;
    if (i < e) {
        atomicAdd(&g_srcdeg[src[i]], 1);
        g_eoff[i] = atomicAdd(&g_rowcnt[dst[i]], 1);
    }
}

// single-block exclusive scan of g_rowcnt -> g_rowptr, fused dinv computation
__global__ void scan_kernel(int n) {
    __shared__ int warp_tot[32];
    __shared__ int carry_sh;
    int t = threadIdx.x, lane = t & 31, wid = t >> 5;
    if (t == 0) carry_sh = 0;
    __syncthreads();
    for (int base = 0; base < n; base += 1024) {
        int i = base + t;
        if (i < n) {
            int d = g_srcdeg[i];
            g_dinv[i] = (d > 0) ? rsqrtf((float)d) : 0.0f;
        }
        int v = (i < n) ? g_rowcnt[i] : 0;
        int x = v;
        #pragma unroll
        for (int off = 1; off < 32; off <<= 1) {
            int y = __shfl_up_sync(0xffffffffu, x, off);
            if (lane >= off) x += y;
        }
        if (lane == 31) warp_tot[wid] = x;
        __syncthreads();
        if (wid == 0) {
            int wt = warp_tot[lane];
            #pragma unroll
            for (int off = 1; off < 32; off <<= 1) {
                int y = __shfl_up_sync(0xffffffffu, wt, off);
                if (lane >= off) wt += y;
            }
            warp_tot[lane] = wt;
        }
        __syncthreads();
        int wp = (wid > 0) ? warp_tot[wid - 1] : 0;
        if (i < n) g_rowptr[i] = carry_sh + wp + x - v;
        __syncthreads();
        if (t == 0) carry_sh += warp_tot[31];
        __syncthreads();
    }
    if (t == 0) g_rowptr[n] = carry_sh;
}

// atomic-free scatter using precomputed offsets
__global__ void scatter_kernel(const int* __restrict__ src, const int* __restrict__ dst, int e) {
    int i = blockIdx.x * blockDim.x + threadIdx.x;
    if (i < e) {
        int s = src[i], d = dst[i];
        float w = -g_dinv[s] * g_dinv[d];
        g_csr[g_rowptr[d] + g_eoff[i]] = make_int2(s, __float_as_int(w));
    }
}

// ---------------- fused SpMM + feature GEMM ----------------
// mode 0: r = (L@H)[row]  -> store T1 = r, U1 = r@A1
// mode 1: r = (L@T1)[row] -> store           U2 = r@A2
// 16 lanes per row; 64 rows per 1024-thread block. GEMM hides in the L2-gather shadow.
__global__ __launch_bounds__(1024, 2) void spmm_fused_kernel(int mode, int layer, int n) {
    const float* __restrict__ X = mode ? g_T1 : g_H;
    float* __restrict__ U       = mode ? g_U2 : g_U1;
    const float* __restrict__ A = g_A + layer * 12288 + (mode ? 8192 : 4096);
    __shared__ float sA[4096];         // 64x64 weight
    __shared__ float sRow[32][2][64];  // per-warp: 2 half-warp rows

    int t = threadIdx.x;
    ((float4*)sA)[t] = ((const float4*)A)[t];   // 1024 threads x float4 = 4096 floats
    __syncthreads();

    int gid  = blockIdx.x * 1024 + t;
    int row  = gid >> 4;
    int lane = gid & 15;
    int wp   = t >> 5;
    int half = (t >> 4) & 1;
    bool valid = row < n;

    float4 r = make_float4(0.f, 0.f, 0.f, 0.f);
    if (valid) {
        int beg = g_rowptr[row], end = g_rowptr[row + 1];
        const float* Xl = X + lane * 4;
        float4 a0 = make_float4(0.f, 0.f, 0.f, 0.f);
        float4 a1 = make_float4(0.f, 0.f, 0.f, 0.f);
        int e = beg;
        for (; e + 2 <= end; e += 2) {
            int2 c0 = g_csr[e];
            int2 c1 = g_csr[e + 1];
            float4 v0 = *(const float4*)(Xl + c0.x * 64);
            float4 v1 = *(const float4*)(Xl + c1.x * 64);
            float w0 = __int_as_float(c0.y), w1 = __int_as_float(c1.y);
            a0.x += w0 * v0.x; a0.y += w0 * v0.y; a0.z += w0 * v0.z; a0.w += w0 * v0.w;
            a1.x += w1 * v1.x; a1.y += w1 * v1.y; a1.z += w1 * v1.z; a1.w += w1 * v1.w;
        }
        if (e < end) {
            int2 c0 = g_csr[e];
            float4 v0 = *(const float4*)(Xl + c0.x * 64);
            float w0 = __int_as_float(c0.y);
            a0.x += w0 * v0.x; a0.y += w0 * v0.y; a0.z += w0 * v0.z; a0.w += w0 * v0.w;
        }
        r.x = a0.x + a1.x; r.y = a0.y + a1.y; r.z = a0.z + a1.z; r.w = a0.w + a1.w;
        *(float4*)&sRow[wp][half][lane * 4] = r;
        if (!mode) *(float4*)(g_T1 + row * 64 + lane * 4) = r;
    }
    __syncwarp();

    if (valid) {
        // u[4 cols c8=lane*4 .. +3] = sum_k row[k] * A[k][c]
        unsigned long long u0 = pack2(0.f, 0.f), u1 = pack2(0.f, 0.f);
        const float* rowp = &sRow[wp][half][0];
        #pragma unroll
        for (int k4 = 0; k4 < 64; k4 += 4) {
            float4 tk = *(const float4*)(rowp + k4);
            #pragma unroll
            for (int q = 0; q < 4; q++) {
                float tv = (q == 0) ? tk.x : (q == 1) ? tk.y : (q == 2) ? tk.z : tk.w;
                float4 a = *(const float4*)&sA[(k4 + q) * 64 + lane * 4];
                unsigned long long t2 = pack2(tv, tv);
                u0 = ffma2(t2, pack2(a.x, a.y), u0);
                u1 = ffma2(t2, pack2(a.z, a.w), u1);
            }
        }
        float2 f0 = unpack2(u0), f1 = unpack2(u1);
        *(float4*)(U + row * 64 + lane * 4) = make_float4(f0.x, f0.y, f1.x, f1.y);
    }
}

// ---------------- input GEMM: g_H = x @ W_in + b_in ----------------
__global__ __launch_bounds__(256) void ingemm_kernel(const float* __restrict__ x,
                                                     const float* __restrict__ Win,
                                                     const float* __restrict__ bin, int n) {
    __shared__ float sW[16 * 64];
    __shared__ float xt[16 * 33];
    __shared__ float so[32 * 65];
    int t = threadIdx.x, lane = t & 31, wg = t >> 5;
    int row0 = blockIdx.x * 32;
    for (int idx = t; idx < 1024; idx += 256) sW[idx] = Win[idx];
    for (int idx = t; idx < 512; idx += 256) {
        int r = idx >> 4, k = idx & 15;
        int row = row0 + r;
        xt[k * 33 + r] = (row < n) ? x[row * 16 + k] : 0.0f;
    }
    __syncthreads();
    float acc[8] = {0, 0, 0, 0, 0, 0, 0, 0};
    #pragma unroll
    for (int k = 0; k < 16; k++) {
        float xv = xt[k * 33 + lane];
        float4 w0 = *(const float4*)&sW[k * 64 + wg * 8];
        float4 w1 = *(const float4*)&sW[k * 64 + wg * 8 + 4];
        acc[0] += xv * w0.x; acc[1] += xv * w0.y; acc[2] += xv * w0.z; acc[3] += xv * w0.w;
        acc[4] += xv * w1.x; acc[5] += xv * w1.y; acc[6] += xv * w1.z; acc[7] += xv * w1.w;
    }
    #pragma unroll
    for (int u = 0; u < 8; u++) {
        int j = wg * 8 + u;
        so[lane * 65 + j] = acc[u] + bin[j];
    }
    __syncthreads();
    int r = t >> 3, c = (t & 7) * 8;
    int row = row0 + r;
    if (row < n) {
        float4 v0, v1;
        v0.x = so[r*65+c+0]; v0.y = so[r*65+c+1]; v0.z = so[r*65+c+2]; v0.w = so[r*65+c+3];
        v1.x = so[r*65+c+4]; v1.y = so[r*65+c+5]; v1.z = so[r*65+c+6]; v1.w = so[r*65+c+7];
        *(float4*)(g_H + row * 64 + c)     = v0;
        *(float4*)(g_H + row * 64 + c + 4) = v1;
    }
}

// ---------------- layer: H' = LN(relu(H@A0 + U1 + U2 + cb) + H) (+ fused out GEMM) ----
#define LK_HT_STRIDE 129
#define LK_HT_FLOATS (64 * LK_HT_STRIDE)          // 8256
#define LK_SMEM_BYTES ((LK_HT_FLOATS + 4096) * 4) // 49408

__global__ __launch_bounds__(256) void layer_kernel(int layer,
                                                    const float* __restrict__ cb,
                                                    const float* __restrict__ lg,
                                                    const float* __restrict__ lbeta,
                                                    const float* __restrict__ Wout,
                                                    const float* __restrict__ bout,
                                                    float* __restrict__ out,
                                                    int last, int n) {
    extern __shared__ float smem[];
    float* ht = smem;                 // [64][129] transposed H tile
    float* sA = smem + LK_HT_FLOATS;  // A0 (64x64)
    __shared__ float sWout[260];

    int t = threadIdx.x;
    int c8 = (t & 7) * 8;
    int rg = t >> 3;
    int row0 = blockIdx.x * 128;
    const float* __restrict__ A = g_A + layer * 12288;

    if (last) {
        sWout[t] = Wout[t];
        if (t < 4) sWout[256 + t] = bout[t];
    }

    unsigned long long acc[4][4];
    #pragma unroll
    for (int i = 0; i < 4; i++)
        #pragma unroll
        for (int j = 0; j < 4; j++) acc[i][j] = pack2(0.0f, 0.0f);

    // stage A0 + transposed H tile
    for (int idx = t; idx < 1024; idx += 256)
        ((float4*)sA)[idx] = ((const float4*)A)[idx];
    for (int idx = t; idx < 2048; idx += 256) {
        int r = idx >> 4, k4 = (idx & 15) * 4;
        int grow = row0 + r;
        float4 v = make_float4(0.f, 0.f, 0.f, 0.f);
        if (grow < n) v = *(const float4*)(g_H + grow * 64 + k4);
        int b = k4 * LK_HT_STRIDE + r;
        ht[b]                    = v.x;
        ht[b + LK_HT_STRIDE]     = v.y;
        ht[b + 2 * LK_HT_STRIDE] = v.z;
        ht[b + 3 * LK_HT_STRIDE] = v.w;
    }
    __syncthreads();
    #pragma unroll 8
    for (int k = 0; k < 64; k++) {
        unsigned long long h2[4];
        #pragma unroll
        for (int i = 0; i < 4; i++) {
            float hv = ht[k * LK_HT_STRIDE + rg * 4 + i];
            h2[i] = pack2(hv, hv);
        }
        float4 wa = *(const float4*)&sA[k * 64 + c8];
        float4 wb = *(const float4*)&sA[k * 64 + c8 + 4];
        unsigned long long w2[4];
        w2[0] = pack2(wa.x, wa.y); w2[1] = pack2(wa.z, wa.w);
        w2[2] = pack2(wb.x, wb.y); w2[3] = pack2(wb.z, wb.w);
        #pragma unroll
        for (int i = 0; i < 4; i++)
            #pragma unroll
            for (int j = 0; j < 4; j++)
                acc[i][j] = ffma2(h2[i], w2[j], acc[i][j]);
    }

    float cbv[8], lgv[8], lbv[8];
    {
        float4 a0 = *(const float4*)(cb + c8),    a1 = *(const float4*)(cb + c8 + 4);
        float4 g0 = *(const float4*)(lg + c8),    g1 = *(const float4*)(lg + c8 + 4);
        float4 b0 = *(const float4*)(lbeta + c8), b1 = *(const float4*)(lbeta + c8 + 4);
        cbv[0]=a0.x;cbv[1]=a0.y;cbv[2]=a0.z;cbv[3]=a0.w;cbv[4]=a1.x;cbv[5]=a1.y;cbv[6]=a1.z;cbv[7]=a1.w;
        lgv[0]=g0.x;lgv[1]=g0.y;lgv[2]=g0.z;lgv[3]=g0.w;lgv[4]=g1.x;lgv[5]=g1.y;lgv[6]=g1.z;lgv[7]=g1.w;
        lbv[0]=b0.x;lbv[1]=b0.y;lbv[2]=b0.z;lbv[3]=b0.w;lbv[4]=b1.x;lbv[5]=b1.y;lbv[6]=b1.z;lbv[7]=b1.w;
    }

    #pragma unroll
    for (int i = 0; i < 4; i++) {
        int grow = row0 + rg * 4 + i;
        float u1v[8], u2v[8];
        if (grow < n) {
            float4 p0 = *(const float4*)(g_U1 + grow * 64 + c8);
            float4 p1 = *(const float4*)(g_U1 + grow * 64 + c8 + 4);
            float4 q0 = *(const float4*)(g_U2 + grow * 64 + c8);
            float4 q1 = *(const float4*)(g_U2 + grow * 64 + c8 + 4);
            u1v[0]=p0.x;u1v[1]=p0.y;u1v[2]=p0.z;u1v[3]=p0.w;
            u1v[4]=p1.x;u1v[5]=p1.y;u1v[6]=p1.z;u1v[7]=p1.w;
            u2v[0]=q0.x;u2v[1]=q0.y;u2v[2]=q0.z;u2v[3]=q0.w;
            u2v[4]=q1.x;u2v[5]=q1.y;u2v[6]=q1.z;u2v[7]=q1.w;
        } else {
            #pragma unroll
            for (int u = 0; u < 8; u++) { u1v[u] = 0.0f; u2v[u] = 0.0f; }
        }
        float val[8];
        #pragma unroll
        for (int j = 0; j < 4; j++) {
            float2 a = unpack2(acc[i][j]);
            float hr0 = ht[(c8 + 2*j)     * LK_HT_STRIDE + rg * 4 + i];
            float hr1 = ht[(c8 + 2*j + 1) * LK_HT_STRIDE + rg * 4 + i];
            val[2*j]   = fmaxf(a.x + u1v[2*j]   + u2v[2*j]   + cbv[2*j],   0.0f) + hr0;
            val[2*j+1] = fmaxf(a.y + u1v[2*j+1] + u2v[2*j+1] + cbv[2*j+1], 0.0f) + hr1;
        }
        float s = 0.0f;
        #pragma unroll
        for (int u = 0; u < 8; u++) s += val[u];
        #pragma unroll
        for (int m = 1; m < 8; m <<= 1) s += __shfl_xor_sync(0xffffffffu, s, m);
        float mu = s * (1.0f / 64.0f);
        float q = 0.0f;
        #pragma unroll
        for (int u = 0; u < 8; u++) { float d = val[u] - mu; q += d * d; }
        #pragma unroll
        for (int m = 1; m < 8; m <<= 1) q += __shfl_xor_sync(0xffffffffu, q, m);
        float rs = rsqrtf(q * (1.0f / 64.0f) + LN_EPS);

        float o[8];
        #pragma unroll
        for (int u = 0; u < 8; u++)
            o[u] = (val[u] - mu) * rs * lgv[u] + lbv[u];

        if (!last) {
            if (grow < n) {
                *(float4*)(g_H + grow * 64 + c8)     = make_float4(o[0], o[1], o[2], o[3]);
                *(float4*)(g_H + grow * 64 + c8 + 4) = make_float4(o[4], o[5], o[6], o[7]);
            }
        } else {
            float4 oa = make_float4(0.f, 0.f, 0.f, 0.f);
            #pragma unroll
            for (int u = 0; u < 8; u++) {
                const float* wr = &sWout[(c8 + u) * 4];
                oa.x += o[u] * wr[0]; oa.y += o[u] * wr[1];
                oa.z += o[u] * wr[2]; oa.w += o[u] * wr[3];
            }
            #pragma unroll
            for (int m = 1; m < 8; m <<= 1) {
                oa.x += __shfl_xor_sync(0xffffffffu, oa.x, m);
                oa.y += __shfl_xor_sync(0xffffffffu, oa.y, m);
                oa.z += __shfl_xor_sync(0xffffffffu, oa.z, m);
                oa.w += __shfl_xor_sync(0xffffffffu, oa.w, m);
            }
            if ((t & 7) == 0 && grow < n) {
                oa.x += sWout[256]; oa.y += sWout[257]; oa.z += sWout[258]; oa.w += sWout[259];
                *(float4*)(out + grow * 4) = oa;
            }
        }
    }
}

// ---------------- launch ----------------
extern "C" void kernel_launch(void* const* d_in, const int* in_sizes, int n_in,
                              void* d_out, int out_size) {
    const float *x = 0, *Win = 0, *bin = 0, *chW = 0, *Wout = 0, *bout = 0;
    const float *p192[3] = {0, 0, 0};
    const int* ei = 0;
    int n192 = 0, e2 = 0, nx = 0;
    for (int i = 0; i < n_in; i++) {
        int sz = in_sizes[i];
        if      (sz == 1600000) { ei = (const int*)d_in[i]; e2 = sz; }
        else if (sz == 800000)  { x = (const float*)d_in[i]; nx = sz; }
        else if (sz == 1024)    Win  = (const float*)d_in[i];
        else if (sz == 64)      bin  = (const float*)d_in[i];
        else if (sz == 36864)   chW  = (const float*)d_in[i];
        else if (sz == 256)     Wout = (const float*)d_in[i];
        else if (sz == 4)       bout = (const float*)d_in[i];
        else if (sz == 192 && n192 < 3) p192[n192++] = (const float*)d_in[i];
    }
    const float* chb = p192[0];
    const float* lng = p192[1];
    const float* lnb = p192[2];
    float* out = (float*)d_out;

    int n = nx / 16;
    int e = e2 / 2;
    const int* src = ei;
    const int* dst = ei + e;

    static cudaStream_t s1 = 0;
    static cudaEvent_t  ev0 = 0, ev1 = 0;
    static int s_init = 0;
    if (!s_init) {
        cudaStreamCreateWithFlags(&s1, cudaStreamNonBlocking);
        cudaEventCreateWithFlags(&ev0, cudaEventDisableTiming);
        cudaEventCreateWithFlags(&ev1, cudaEventDisableTiming);
        cudaFuncSetAttribute(layer_kernel, cudaFuncAttributeMaxDynamicSharedMemorySize,
                             LK_SMEM_BYTES);
        s_init = 1;
    }

    cudaStream_t s0 = 0;
    int ingemm_blocks = (n + 31) / 32;
    int layer_blocks  = (n + 127) / 128;
    int spmm_blocks   = (n * 16 + 1023) / 1024;

    // fork: prepA + ingemm concurrent with CSR build (independent inputs)
    cudaEventRecord(ev0, s0);
    cudaStreamWaitEvent(s1, ev0, 0);
    prepA_kernel<<<(3 * 4096 + 255) / 256, 256, 0, s1>>>(chW);
    ingemm_kernel<<<ingemm_blocks, 256, 0, s1>>>(x, Win, bin, n);
    cudaEventRecord(ev1, s1);

    zero_kernel<<<(n + 255) / 256, 256, 0, s0>>>(n);
    count_kernel<<<(e + 255) / 256, 256, 0, s0>>>(src, dst, e);
    scan_kernel<<<1, 1024, 0, s0>>>(n);          // fused dinv
    scatter_kernel<<<(e + 255) / 256, 256, 0, s0>>>(src, dst, e);
    cudaStreamWaitEvent(s0, ev1, 0);

    for (int i = 0; i < 3; i++) {
        spmm_fused_kernel<<<spmm_blocks, 1024, 0, s0>>>(0, i, n);  // T1, U1
        spmm_fused_kernel<<<spmm_blocks, 1024, 0, s0>>>(1, i, n);  // U2
        layer_kernel<<<layer_blocks, 256, LK_SMEM_BYTES, s0>>>(
            i, chb + i * 64, lng + i * 64, lnb + i * 64,
            Wout, bout, out, (i == 2) ? 1 : 0, n);
    }
}

// round 6
// speedup vs baseline: 1.9568x; 1.9568x over previous
#include <cuda_runtime.h>

#define NMAX 50000
#define EMAX 800000
#define HIDDIM 64
#define LN_EPS 1e-5f

// ---------------- scratch (device globals; no allocation allowed) ----------------
__device__ __align__(16) int   g_srcdeg[NMAX];
__device__ __align__(16) int   g_rowcnt[NMAX];
__device__ __align__(16) int   g_rowptr[NMAX + 1];
__device__ __align__(16) int   g_eoff[EMAX];             // per-edge intra-row slot
__device__ __align__(16) float g_dinv[NMAX];
__device__ __align__(16) int2  g_csr[EMAX];              // {src, bitcast(w)} grouped by dst
__device__ __align__(16) float g_H [NMAX * HIDDIM];
__device__ __align__(16) float g_T1[NMAX * HIDDIM];
__device__ __align__(16) float g_T2[NMAX * HIDDIM];
__device__ __align__(16) float g_A [3 * 3 * HIDDIM * HIDDIM];  // folded weights per layer

// ---------------- f32x2 packed-FMA helpers (sm_100+ PTX) ----------------
__device__ __forceinline__ unsigned long long pack2(float a, float b) {
    unsigned long long r;
    asm("mov.b64 %0, {%1, %2};" : "=l"(r) : "f"(a), "f"(b));
    return r;
}
__device__ __forceinline__ unsigned long long ffma2(unsigned long long a,
                                                    unsigned long long b,
                                                    unsigned long long c) {
    unsigned long long d;
    asm("fma.rn.f32x2 %0, %1, %2, %3;" : "=l"(d) : "l"(a), "l"(b), "l"(c));
    return d;
}
__device__ __forceinline__ float2 unpack2(unsigned long long v) {
    float2 f;
    asm("mov.b64 {%0, %1}, %2;" : "=f"(f.x), "=f"(f.y) : "l"(v));
    return f;
}

// ---------------- weight folding: A0 = W0 - W2, A1 = W1, A2 = 2*W2 ----------------
__global__ void prepA_kernel(const float* __restrict__ W) {
    int idx = blockIdx.x * blockDim.x + threadIdx.x;
    if (idx < 3 * 4096) {
        int i = idx >> 12, r = idx & 4095;
        const float* Wi = W + i * 3 * 4096;
        float w0 = Wi[r], w1 = Wi[4096 + r], w2 = Wi[8192 + r];
        float* Ai = g_A + i * 3 * 4096;
        Ai[r]        = w0 - w2;
        Ai[4096 + r] = w1;
        Ai[8192 + r] = 2.0f * w2;
    }
}

__global__ void zero_kernel(int n) {
    int i = blockIdx.x * blockDim.x + threadIdx.x;
    if (i < n) { g_srcdeg[i] = 0; g_rowcnt[i] = 0; }
}

// scalar, 1 edge/thread (proven fastest); atomic return value = intra-row slot
__global__ void count_kernel(const int* __restrict__ src, const int* __restrict__ dst, int e) {
    int i = blockIdx.x * blockDim.x + threadIdx.x;
    if (i < e) {
        atomicAdd(&g_srcdeg[src[i]], 1);
        g_eoff[i] = atomicAdd(&g_rowcnt[dst[i]], 1);
    }
}

// single-block exclusive scan of g_rowcnt -> g_rowptr, fused dinv computation
__global__ void scan_kernel(int n) {
    __shared__ int warp_tot[32];
    __shared__ int carry_sh;
    int t = threadIdx.x, lane = t & 31, wid = t >> 5;
    if (t == 0) carry_sh = 0;
    __syncthreads();
    for (int base = 0; base < n; base += 1024) {
        int i = base + t;
        if (i < n) {
            int d = g_srcdeg[i];
            g_dinv[i] = (d > 0) ? rsqrtf((float)d) : 0.0f;
        }
        int v = (i < n) ? g_rowcnt[i] : 0;
        int x = v;
        #pragma unroll
        for (int off = 1; off < 32; off <<= 1) {
            int y = __shfl_up_sync(0xffffffffu, x, off);
            if (lane >= off) x += y;
        }
        if (lane == 31) warp_tot[wid] = x;
        __syncthreads();
        if (wid == 0) {
            int wt = warp_tot[lane];
            #pragma unroll
            for (int off = 1; off < 32; off <<= 1) {
                int y = __shfl_up_sync(0xffffffffu, wt, off);
                if (lane >= off) wt += y;
            }
            warp_tot[lane] = wt;
        }
        __syncthreads();
        int wp = (wid > 0) ? warp_tot[wid - 1] : 0;
        if (i < n) g_rowptr[i] = carry_sh + wp + x - v;
        __syncthreads();
        if (t == 0) carry_sh += warp_tot[31];
        __syncthreads();
    }
    if (t == 0) g_rowptr[n] = carry_sh;
}

// atomic-free scatter using precomputed slots
__global__ void scatter_kernel(const int* __restrict__ src, const int* __restrict__ dst, int e) {
    int i = blockIdx.x * blockDim.x + threadIdx.x;
    if (i < e) {
        int s = src[i], d = dst[i];
        float w = -g_dinv[s] * g_dinv[d];
        g_csr[g_rowptr[d] + g_eoff[i]] = make_int2(s, __float_as_int(w));
    }
}

// ---------------- SpMM: Y[dst] = sum_e w * X[src]  (16 threads per row) ----------------
__global__ __launch_bounds__(256) void spmm_kernel(int mode, int n) {
    const float* __restrict__ X = mode ? g_T1 : g_H;
    float* __restrict__ Y       = mode ? g_T2 : g_T1;
    int gid  = blockIdx.x * blockDim.x + threadIdx.x;
    int row  = gid >> 4;
    int lane = gid & 15;
    if (row >= n) return;
    int beg = g_rowptr[row], end = g_rowptr[row + 1];
    float4 a0 = make_float4(0.f, 0.f, 0.f, 0.f);
    float4 a1 = make_float4(0.f, 0.f, 0.f, 0.f);
    int e = beg;
    for (; e + 2 <= end; e += 2) {
        int2 c0 = g_csr[e];
        int2 c1 = g_csr[e + 1];
        float4 v0 = *(const float4*)(X + c0.x * HIDDIM + lane * 4);
        float4 v1 = *(const float4*)(X + c1.x * HIDDIM + lane * 4);
        float w0 = __int_as_float(c0.y), w1 = __int_as_float(c1.y);
        a0.x += w0 * v0.x; a0.y += w0 * v0.y; a0.z += w0 * v0.z; a0.w += w0 * v0.w;
        a1.x += w1 * v1.x; a1.y += w1 * v1.y; a1.z += w1 * v1.z; a1.w += w1 * v1.w;
    }
    if (e < end) {
        int2 c0 = g_csr[e];
        float4 v0 = *(const float4*)(X + c0.x * HIDDIM + lane * 4);
        float w0 = __int_as_float(c0.y);
        a0.x += w0 * v0.x; a0.y += w0 * v0.y; a0.z += w0 * v0.z; a0.w += w0 * v0.w;
    }
    float4 r;
    r.x = a0.x + a1.x; r.y = a0.y + a1.y; r.z = a0.z + a1.z; r.w = a0.w + a1.w;
    *(float4*)(Y + row * HIDDIM + lane * 4) = r;
}

// ---------------- input GEMM: g_H = x @ W_in + b_in ----------------
__global__ __launch_bounds__(256) void ingemm_kernel(const float* __restrict__ x,
                                                     const float* __restrict__ Win,
                                                     const float* __restrict__ bin, int n) {
    __shared__ float sW[16 * 64];
    __shared__ float xt[16 * 33];
    __shared__ float so[32 * 65];
    int t = threadIdx.x, lane = t & 31, wg = t >> 5;
    int row0 = blockIdx.x * 32;
    for (int idx = t; idx < 1024; idx += 256) sW[idx] = Win[idx];
    for (int idx = t; idx < 512; idx += 256) {
        int r = idx >> 4, k = idx & 15;
        int row = row0 + r;
        xt[k * 33 + r] = (row < n) ? x[row * 16 + k] : 0.0f;
    }
    __syncthreads();
    float acc[8] = {0, 0, 0, 0, 0, 0, 0, 0};
    #pragma unroll
    for (int k = 0; k < 16; k++) {
        float xv = xt[k * 33 + lane];
        float4 w0 = *(const float4*)&sW[k * 64 + wg * 8];
        float4 w1 = *(const float4*)&sW[k * 64 + wg * 8 + 4];
        acc[0] += xv * w0.x; acc[1] += xv * w0.y; acc[2] += xv * w0.z; acc[3] += xv * w0.w;
        acc[4] += xv * w1.x; acc[5] += xv * w1.y; acc[6] += xv * w1.z; acc[7] += xv * w1.w;
    }
    #pragma unroll
    for (int u = 0; u < 8; u++) {
        int j = wg * 8 + u;
        so[lane * 65 + j] = acc[u] + bin[j];
    }
    __syncthreads();
    int r = t >> 3, c = (t & 7) * 8;
    int row = row0 + r;
    if (row < n) {
        float4 v0, v1;
        v0.x = so[r*65+c+0]; v0.y = so[r*65+c+1]; v0.z = so[r*65+c+2]; v0.w = so[r*65+c+3];
        v1.x = so[r*65+c+4]; v1.y = so[r*65+c+5]; v1.z = so[r*65+c+6]; v1.w = so[r*65+c+7];
        *(float4*)(g_H + row * 64 + c)     = v0;
        *(float4*)(g_H + row * 64 + c + 4) = v1;
    }
}

// ---------------- fused layer (128 rows/block, f32x2 FMA, fused out-GEMM on last) ----
// H = LN(relu(H@A0 + T1@A1 + T2@A2 + cb) + H) ; if last: out = H@Wout + bout (no g_H store)
#define LK_HT_STRIDE 129
#define LK_HT_FLOATS (64 * LK_HT_STRIDE)          // 8256
#define LK_SMEM_BYTES ((LK_HT_FLOATS + 4096) * 4) // 49408

__global__ __launch_bounds__(256) void layer_kernel(int layer,
                                                    const float* __restrict__ cb,
                                                    const float* __restrict__ lg,
                                                    const float* __restrict__ lbeta,
                                                    const float* __restrict__ Wout,
                                                    const float* __restrict__ bout,
                                                    float* __restrict__ out,
                                                    int last, int n) {
    extern __shared__ float smem[];
    float* ht = smem;                 // [64][129] transposed tile
    float* sA = smem + LK_HT_FLOATS;  // [64][64] current weight matrix
    __shared__ float sWout[260];

    int t = threadIdx.x;
    int c8 = (t & 7) * 8;             // column group (8 cols)
    int rg = t >> 3;                  // row group (4 rows)
    int row0 = blockIdx.x * 128;
    const float* __restrict__ A = g_A + layer * 12288;

    if (last) {
        sWout[t] = Wout[t];
        if (t < 4) sWout[256 + t] = bout[t];
    }

    unsigned long long acc[4][4];
    #pragma unroll
    for (int i = 0; i < 4; i++)
        #pragma unroll
        for (int j = 0; j < 4; j++) acc[i][j] = pack2(0.0f, 0.0f);

    #pragma unroll
    for (int pass = 0; pass < 3; pass++) {
        const float* __restrict__ S = (pass == 0) ? g_H : ((pass == 1) ? g_T1 : g_T2);
        for (int idx = t; idx < 1024; idx += 256)
            ((float4*)sA)[idx] = ((const float4*)(A + pass * 4096))[idx];
        for (int idx = t; idx < 2048; idx += 256) {
            int r = idx >> 4, k4 = (idx & 15) * 4;
            int grow = row0 + r;
            float4 v = make_float4(0.f, 0.f, 0.f, 0.f);
            if (grow < n) v = *(const float4*)(S + grow * 64 + k4);
            int b = k4 * LK_HT_STRIDE + r;
            ht[b]                    = v.x;
            ht[b + LK_HT_STRIDE]     = v.y;
            ht[b + 2 * LK_HT_STRIDE] = v.z;
            ht[b + 3 * LK_HT_STRIDE] = v.w;
        }
        __syncthreads();
        #pragma unroll 8
        for (int k = 0; k < 64; k++) {
            unsigned long long h2[4];
            #pragma unroll
            for (int i = 0; i < 4; i++) {
                float hv = ht[k * LK_HT_STRIDE + rg * 4 + i];
                h2[i] = pack2(hv, hv);
            }
            float4 wa = *(const float4*)&sA[k * 64 + c8];
            float4 wb = *(const float4*)&sA[k * 64 + c8 + 4];
            unsigned long long w2[4];
            w2[0] = pack2(wa.x, wa.y); w2[1] = pack2(wa.z, wa.w);
            w2[2] = pack2(wb.x, wb.y); w2[3] = pack2(wb.z, wb.w);
            #pragma unroll
            for (int i = 0; i < 4; i++)
                #pragma unroll
                for (int j = 0; j < 4; j++)
                    acc[i][j] = ffma2(h2[i], w2[j], acc[i][j]);
        }
        __syncthreads();
    }

    // ---- epilogue: bias + relu + residual + layernorm (+ fused out-GEMM) ----
    float cbv[8], lgv[8], lbv[8];
    {
        float4 a0 = *(const float4*)(cb + c8),    a1 = *(const float4*)(cb + c8 + 4);
        float4 g0 = *(const float4*)(lg + c8),    g1 = *(const float4*)(lg + c8 + 4);
        float4 b0 = *(const float4*)(lbeta + c8), b1 = *(const float4*)(lbeta + c8 + 4);
        cbv[0]=a0.x;cbv[1]=a0.y;cbv[2]=a0.z;cbv[3]=a0.w;cbv[4]=a1.x;cbv[5]=a1.y;cbv[6]=a1.z;cbv[7]=a1.w;
        lgv[0]=g0.x;lgv[1]=g0.y;lgv[2]=g0.z;lgv[3]=g0.w;lgv[4]=g1.x;lgv[5]=g1.y;lgv[6]=g1.z;lgv[7]=g1.w;
        lbv[0]=b0.x;lbv[1]=b0.y;lbv[2]=b0.z;lbv[3]=b0.w;lbv[4]=b1.x;lbv[5]=b1.y;lbv[6]=b1.z;lbv[7]=b1.w;
    }

    #pragma unroll
    for (int i = 0; i < 4; i++) {
        int grow = row0 + rg * 4 + i;
        float hres[8];
        if (grow < n) {
            float4 r0 = *(const float4*)(g_H + grow * 64 + c8);
            float4 r1 = *(const float4*)(g_H + grow * 64 + c8 + 4);
            hres[0]=r0.x;hres[1]=r0.y;hres[2]=r0.z;hres[3]=r0.w;
            hres[4]=r1.x;hres[5]=r1.y;hres[6]=r1.z;hres[7]=r1.w;
        } else {
            #pragma unroll
            for (int u = 0; u < 8; u++) hres[u] = 0.0f;
        }
        float val[8];
        #pragma unroll
        for (int j = 0; j < 4; j++) {
            float2 a = unpack2(acc[i][j]);
            val[2*j]   = fmaxf(a.x + cbv[2*j],   0.0f) + hres[2*j];
            val[2*j+1] = fmaxf(a.y + cbv[2*j+1], 0.0f) + hres[2*j+1];
        }
        float s = 0.0f;
        #pragma unroll
        for (int u = 0; u < 8; u++) s += val[u];
        #pragma unroll
        for (int m = 1; m < 8; m <<= 1) s += __shfl_xor_sync(0xffffffffu, s, m);
        float mu = s * (1.0f / 64.0f);
        float q = 0.0f;
        #pragma unroll
        for (int u = 0; u < 8; u++) { float d = val[u] - mu; q += d * d; }
        #pragma unroll
        for (int m = 1; m < 8; m <<= 1) q += __shfl_xor_sync(0xffffffffu, q, m);
        float rs = rsqrtf(q * (1.0f / 64.0f) + LN_EPS);

        float o[8];
        #pragma unroll
        for (int u = 0; u < 8; u++)
            o[u] = (val[u] - mu) * rs * lgv[u] + lbv[u];

        if (!last) {
            if (grow < n) {
                *(float4*)(g_H + grow * 64 + c8)     = make_float4(o[0], o[1], o[2], o[3]);
                *(float4*)(g_H + grow * 64 + c8 + 4) = make_float4(o[4], o[5], o[6], o[7]);
            }
        } else {
            float4 oa = make_float4(0.f, 0.f, 0.f, 0.f);
            #pragma unroll
            for (int u = 0; u < 8; u++) {
                const float* wr = &sWout[(c8 + u) * 4];
                oa.x += o[u] * wr[0]; oa.y += o[u] * wr[1];
                oa.z += o[u] * wr[2]; oa.w += o[u] * wr[3];
            }
            #pragma unroll
            for (int m = 1; m < 8; m <<= 1) {
                oa.x += __shfl_xor_sync(0xffffffffu, oa.x, m);
                oa.y += __shfl_xor_sync(0xffffffffu, oa.y, m);
                oa.z += __shfl_xor_sync(0xffffffffu, oa.z, m);
                oa.w += __shfl_xor_sync(0xffffffffu, oa.w, m);
            }
            if ((t & 7) == 0 && grow < n) {
                oa.x += sWout[256]; oa.y += sWout[257]; oa.z += sWout[258]; oa.w += sWout[259];
                *(float4*)(out + grow * 4) = oa;
            }
        }
    }
}

// ---------------- launch ----------------
extern "C" void kernel_launch(void* const* d_in, const int* in_sizes, int n_in,
                              void* d_out, int out_size) {
    const float *x = 0, *Win = 0, *bin = 0, *chW = 0, *Wout = 0, *bout = 0;
    const float *p192[3] = {0, 0, 0};
    const int* ei = 0;
    int n192 = 0, e2 = 0, nx = 0;
    for (int i = 0; i < n_in; i++) {
        int sz = in_sizes[i];
        if      (sz == 1600000) { ei = (const int*)d_in[i]; e2 = sz; }
        else if (sz == 800000)  { x = (const float*)d_in[i]; nx = sz; }
        else if (sz == 1024)    Win  = (const float*)d_in[i];
        else if (sz == 64)      bin  = (const float*)d_in[i];
        else if (sz == 36864)   chW  = (const float*)d_in[i];
        else if (sz == 256)     Wout = (const float*)d_in[i];
        else if (sz == 4)       bout = (const float*)d_in[i];
        else if (sz == 192 && n192 < 3) p192[n192++] = (const float*)d_in[i];
    }
    const float* chb = p192[0];
    const float* lng = p192[1];
    const float* lnb = p192[2];
    float* out = (float*)d_out;

    int n = nx / 16;
    int e = e2 / 2;
    const int* src = ei;
    const int* dst = ei + e;

    static cudaStream_t s1 = 0;
    static cudaEvent_t  ev0 = 0, ev1 = 0;
    static int s_init = 0;
    if (!s_init) {
        cudaStreamCreateWithFlags(&s1, cudaStreamNonBlocking);
        cudaEventCreateWithFlags(&ev0, cudaEventDisableTiming);
        cudaEventCreateWithFlags(&ev1, cudaEventDisableTiming);
        cudaFuncSetAttribute(layer_kernel, cudaFuncAttributeMaxDynamicSharedMemorySize,
                             LK_SMEM_BYTES);
        s_init = 1;
    }

    cudaStream_t s0 = 0;
    int ingemm_blocks = (n + 31) / 32;
    int layer_blocks  = (n + 127) / 128;
    int spmm_blocks   = (n * 16 + 255) / 256;

    // fork: prepA + ingemm concurrent with CSR build (independent inputs)
    cudaEventRecord(ev0, s0);
    cudaStreamWaitEvent(s1, ev0, 0);
    prepA_kernel<<<(3 * 4096 + 255) / 256, 256, 0, s1>>>(chW);
    ingemm_kernel<<<ingemm_blocks, 256, 0, s1>>>(x, Win, bin, n);
    cudaEventRecord(ev1, s1);

    // CSR build (default stream)
    zero_kernel<<<(n + 255) / 256, 256, 0, s0>>>(n);
    count_kernel<<<(e + 255) / 256, 256, 0, s0>>>(src, dst, e);
    scan_kernel<<<1, 1024, 0, s0>>>(n);          // fused dinv
    scatter_kernel<<<(e + 255) / 256, 256, 0, s0>>>(src, dst, e);
    cudaStreamWaitEvent(s0, ev1, 0);

    for (int i = 0; i < 3; i++) {
        spmm_kernel<<<spmm_blocks, 256, 0, s0>>>(0, n);  // T1 = L_hat @ H
        spmm_kernel<<<spmm_blocks, 256, 0, s0>>>(1, n);  // T2 = L_hat @ T1
        layer_kernel<<<layer_blocks, 256, LK_SMEM_BYTES, s0>>>(
            i, chb + i * 64, lng + i * 64, lnb + i * 64,
            Wout, bout, out, (i == 2) ? 1 : 0, n);
    }
}

// round 7
// speedup vs baseline: 2.1281x; 1.0875x over previous
#include <cuda_runtime.h>

#define NMAX 50000
#define EMAX 800000
#define HIDDIM 64
#define LN_EPS 1e-5f

// ---------------- scratch (device globals; no allocation allowed) ----------------
// Counter arrays (g_srcdeg, g_rowcnt, g_cursor) are SELF-CLEANING: they are
// zero at module load, and every launch re-zeroes them inside scan_kernel
// after use, so each launch (correctness run + every graph replay) starts
// from the same zeroed state without a dedicated zero kernel.
__device__ __align__(16) int   g_srcdeg[NMAX];
__device__ __align__(16) int   g_rowcnt[NMAX];
__device__ __align__(16) int   g_cursor[NMAX];
__device__ __align__(16) int   g_rowptr[NMAX + 1];
__device__ __align__(16) float g_dinv[NMAX];
__device__ __align__(16) int2  g_csr[EMAX];              // {src, bitcast(w)} grouped by dst
__device__ __align__(16) float g_H [NMAX * HIDDIM];
__device__ __align__(16) float g_T1[NMAX * HIDDIM];
__device__ __align__(16) float g_T2[NMAX * HIDDIM];
__device__ __align__(16) float g_A [3 * 3 * HIDDIM * HIDDIM];  // folded weights per layer

// ---------------- f32x2 packed-FMA helpers (sm_100+ PTX) ----------------
__device__ __forceinline__ unsigned long long pack2(float a, float b) {
    unsigned long long r;
    asm("mov.b64 %0, {%1, %2};" : "=l"(r) : "f"(a), "f"(b));
    return r;
}
__device__ __forceinline__ unsigned long long ffma2(unsigned long long a,
                                                    unsigned long long b,
                                                    unsigned long long c) {
    unsigned long long d;
    asm("fma.rn.f32x2 %0, %1, %2, %3;" : "=l"(d) : "l"(a), "l"(b), "l"(c));
    return d;
}
__device__ __forceinline__ float2 unpack2(unsigned long long v) {
    float2 f;
    asm("mov.b64 {%0, %1}, %2;" : "=f"(f.x), "=f"(f.y) : "l"(v));
    return f;
}

// ---------------- weight folding: A0 = W0 - W2, A1 = W1, A2 = 2*W2 ----------------
__global__ void prepA_kernel(const float* __restrict__ W) {
    int idx = blockIdx.x * blockDim.x + threadIdx.x;
    if (idx < 3 * 4096) {
        int i = idx >> 12, r = idx & 4095;
        const float* Wi = W + i * 3 * 4096;
        float w0 = Wi[r], w1 = Wi[4096 + r], w2 = Wi[8192 + r];
        float* Ai = g_A + i * 3 * 4096;
        Ai[r]        = w0 - w2;
        Ai[4096 + r] = w1;
        Ai[8192 + r] = 2.0f * w2;
    }
}

// scalar, 1 edge/thread (measured fastest across rounds)
__global__ void count_kernel(const int* __restrict__ src, const int* __restrict__ dst, int e) {
    int i = blockIdx.x * blockDim.x + threadIdx.x;
    if (i < e) {
        atomicAdd(&g_srcdeg[src[i]], 1);
        atomicAdd(&g_rowcnt[dst[i]], 1);
    }
}

// single-block scan, int4-vectorized (4096 elems/iteration):
//   rowcnt -> rowptr (exclusive), srcdeg -> dinv, and zero all counters for
//   the next launch (cursor must be zero before scatter below).
__global__ void scan_kernel(int n) {
    __shared__ int warp_tot[32];
    __shared__ int carry_sh;
    int t = threadIdx.x, lane = t & 31, wid = t >> 5;
    if (t == 0) carry_sh = 0;
    __syncthreads();
    int nv = n & ~3;  // vectorized portion (int4-aligned)
    const int4 zero4 = make_int4(0, 0, 0, 0);
    for (int base = 0; base < nv; base += 4096) {
        int i = base + t * 4;
        bool act = i < nv;
        int4 v = zero4;
        if (act) {
            v = *(const int4*)(g_rowcnt + i);
            *(int4*)(g_rowcnt + i) = zero4;
            int4 dg = *(const int4*)(g_srcdeg + i);
            *(int4*)(g_srcdeg + i) = zero4;
            *(int4*)(g_cursor + i) = zero4;
            float4 dv;
            dv.x = (dg.x > 0) ? rsqrtf((float)dg.x) : 0.0f;
            dv.y = (dg.y > 0) ? rsqrtf((float)dg.y) : 0.0f;
            dv.z = (dg.z > 0) ? rsqrtf((float)dg.z) : 0.0f;
            dv.w = (dg.w > 0) ? rsqrtf((float)dg.w) : 0.0f;
            *(float4*)(g_dinv + i) = dv;
        }
        int tsum = v.x + v.y + v.z + v.w;
        int x = tsum;
        #pragma unroll
        for (int off = 1; off < 32; off <<= 1) {
            int y = __shfl_up_sync(0xffffffffu, x, off);
            if (lane >= off) x += y;
        }
        if (lane == 31) warp_tot[wid] = x;
        __syncthreads();
        if (wid == 0) {
            int wt = warp_tot[lane];
            #pragma unroll
            for (int off = 1; off < 32; off <<= 1) {
                int y = __shfl_up_sync(0xffffffffu, wt, off);
                if (lane >= off) wt += y;
            }
            warp_tot[lane] = wt;
        }
        __syncthreads();
        int wp = (wid > 0) ? warp_tot[wid - 1] : 0;
        if (act) {
            int excl = carry_sh + wp + (x - tsum);
            int4 rp;
            rp.x = excl;
            rp.y = excl + v.x;
            rp.z = excl + v.x + v.y;
            rp.w = excl + v.x + v.y + v.z;
            *(int4*)(g_rowptr + i) = rp;
        }
        __syncthreads();
        if (t == 0) carry_sh += warp_tot[31];
        __syncthreads();
    }
    // scalar tail + sentinel (thread 0)
    if (t == 0) {
        int c = carry_sh;
        for (int i = nv; i < n; i++) {
            int d = g_srcdeg[i];
            g_dinv[i] = (d > 0) ? rsqrtf((float)d) : 0.0f;
            g_srcdeg[i] = 0;
            g_cursor[i] = 0;
            g_rowptr[i] = c;
            c += g_rowcnt[i];
            g_rowcnt[i] = 0;
        }
        g_rowptr[n] = c;
    }
}

__global__ void scatter_kernel(const int* __restrict__ src, const int* __restrict__ dst, int e) {
    int i = blockIdx.x * blockDim.x + threadIdx.x;
    if (i < e) {
        int s = src[i], d = dst[i];
        float w = -g_dinv[s] * g_dinv[d];
        int pos = g_rowptr[d] + atomicAdd(&g_cursor[d], 1);
        g_csr[pos] = make_int2(s, __float_as_int(w));
    }
}

// ---------------- SpMM: Y[dst] = sum_e w * X[src]  (16 threads per row) ----------------
__global__ __launch_bounds__(256) void spmm_kernel(int mode, int n) {
    const float* __restrict__ X = mode ? g_T1 : g_H;
    float* __restrict__ Y       = mode ? g_T2 : g_T1;
    int gid  = blockIdx.x * blockDim.x + threadIdx.x;
    int row  = gid >> 4;
    int lane = gid & 15;
    if (row >= n) return;
    int beg = g_rowptr[row], end = g_rowptr[row + 1];
    float4 a0 = make_float4(0.f, 0.f, 0.f, 0.f);
    float4 a1 = make_float4(0.f, 0.f, 0.f, 0.f);
    int e = beg;
    for (; e + 2 <= end; e += 2) {
        int2 c0 = g_csr[e];
        int2 c1 = g_csr[e + 1];
        float4 v0 = *(const float4*)(X + c0.x * HIDDIM + lane * 4);
        float4 v1 = *(const float4*)(X + c1.x * HIDDIM + lane * 4);
        float w0 = __int_as_float(c0.y), w1 = __int_as_float(c1.y);
        a0.x += w0 * v0.x; a0.y += w0 * v0.y; a0.z += w0 * v0.z; a0.w += w0 * v0.w;
        a1.x += w1 * v1.x; a1.y += w1 * v1.y; a1.z += w1 * v1.z; a1.w += w1 * v1.w;
    }
    if (e < end) {
        int2 c0 = g_csr[e];
        float4 v0 = *(const float4*)(X + c0.x * HIDDIM + lane * 4);
        float w0 = __int_as_float(c0.y);
        a0.x += w0 * v0.x; a0.y += w0 * v0.y; a0.z += w0 * v0.z; a0.w += w0 * v0.w;
    }
    float4 r;
    r.x = a0.x + a1.x; r.y = a0.y + a1.y; r.z = a0.z + a1.z; r.w = a0.w + a1.w;
    *(float4*)(Y + row * HIDDIM + lane * 4) = r;
}

// ---------------- input GEMM: g_H = x @ W_in + b_in ----------------
__global__ __launch_bounds__(256) void ingemm_kernel(const float* __restrict__ x,
                                                     const float* __restrict__ Win,
                                                     const float* __restrict__ bin, int n) {
    __shared__ float sW[16 * 64];
    __shared__ float xt[16 * 33];
    __shared__ float so[32 * 65];
    int t = threadIdx.x, lane = t & 31, wg = t >> 5;
    int row0 = blockIdx.x * 32;
    for (int idx = t; idx < 1024; idx += 256) sW[idx] = Win[idx];
    for (int idx = t; idx < 512; idx += 256) {
        int r = idx >> 4, k = idx & 15;
        int row = row0 + r;
        xt[k * 33 + r] = (row < n) ? x[row * 16 + k] : 0.0f;
    }
    __syncthreads();
    float acc[8] = {0, 0, 0, 0, 0, 0, 0, 0};
    #pragma unroll
    for (int k = 0; k < 16; k++) {
        float xv = xt[k * 33 + lane];
        float4 w0 = *(const float4*)&sW[k * 64 + wg * 8];
        float4 w1 = *(const float4*)&sW[k * 64 + wg * 8 + 4];
        acc[0] += xv * w0.x; acc[1] += xv * w0.y; acc[2] += xv * w0.z; acc[3] += xv * w0.w;
        acc[4] += xv * w1.x; acc[5] += xv * w1.y; acc[6] += xv * w1.z; acc[7] += xv * w1.w;
    }
    #pragma unroll
    for (int u = 0; u < 8; u++) {
        int j = wg * 8 + u;
        so[lane * 65 + j] = acc[u] + bin[j];
    }
    __syncthreads();
    int r = t >> 3, c = (t & 7) * 8;
    int row = row0 + r;
    if (row < n) {
        float4 v0, v1;
        v0.x = so[r*65+c+0]; v0.y = so[r*65+c+1]; v0.z = so[r*65+c+2]; v0.w = so[r*65+c+3];
        v1.x = so[r*65+c+4]; v1.y = so[r*65+c+5]; v1.z = so[r*65+c+6]; v1.w = so[r*65+c+7];
        *(float4*)(g_H + row * 64 + c)     = v0;
        *(float4*)(g_H + row * 64 + c + 4) = v1;
    }
}

// ---------------- fused layer (128 rows/block, f32x2 FMA, fused out-GEMM on last) ----
// H = LN(relu(H@A0 + T1@A1 + T2@A2 + cb) + H) ; if last: out = H@Wout + bout (no g_H store)
#define LK_HT_STRIDE 129
#define LK_HT_FLOATS (64 * LK_HT_STRIDE)          // 8256
#define LK_SMEM_BYTES ((LK_HT_FLOATS + 4096) * 4) // 49408

__global__ __launch_bounds__(256) void layer_kernel(int layer,
                                                    const float* __restrict__ cb,
                                                    const float* __restrict__ lg,
                                                    const float* __restrict__ lbeta,
                                                    const float* __restrict__ Wout,
                                                    const float* __restrict__ bout,
                                                    float* __restrict__ out,
                                                    int last, int n) {
    extern __shared__ float smem[];
    float* ht = smem;                 // [64][129] transposed tile
    float* sA = smem + LK_HT_FLOATS;  // [64][64] current weight matrix
    __shared__ float sWout[260];

    int t = threadIdx.x;
    int c8 = (t & 7) * 8;             // column group (8 cols)
    int rg = t >> 3;                  // row group (4 rows)
    int row0 = blockIdx.x * 128;
    const float* __restrict__ A = g_A + layer * 12288;

    if (last) {
        sWout[t] = Wout[t];
        if (t < 4) sWout[256 + t] = bout[t];
    }

    unsigned long long acc[4][4];
    #pragma unroll
    for (int i = 0; i < 4; i++)
        #pragma unroll
        for (int j = 0; j < 4; j++) acc[i][j] = pack2(0.0f, 0.0f);

    #pragma unroll
    for (int pass = 0; pass < 3; pass++) {
        const float* __restrict__ S = (pass == 0) ? g_H : ((pass == 1) ? g_T1 : g_T2);
        for (int idx = t; idx < 1024; idx += 256)
            ((float4*)sA)[idx] = ((const float4*)(A + pass * 4096))[idx];
        for (int idx = t; idx < 2048; idx += 256) {
            int r = idx >> 4, k4 = (idx & 15) * 4;
            int grow = row0 + r;
            float4 v = make_float4(0.f, 0.f, 0.f, 0.f);
            if (grow < n) v = *(const float4*)(S + grow * 64 + k4);
            int b = k4 * LK_HT_STRIDE + r;
            ht[b]                    = v.x;
            ht[b + LK_HT_STRIDE]     = v.y;
            ht[b + 2 * LK_HT_STRIDE] = v.z;
            ht[b + 3 * LK_HT_STRIDE] = v.w;
        }
        __syncthreads();
        #pragma unroll 8
        for (int k = 0; k < 64; k++) {
            unsigned long long h2[4];
            #pragma unroll
            for (int i = 0; i < 4; i++) {
                float hv = ht[k * LK_HT_STRIDE + rg * 4 + i];
                h2[i] = pack2(hv, hv);
            }
            float4 wa = *(const float4*)&sA[k * 64 + c8];
            float4 wb = *(const float4*)&sA[k * 64 + c8 + 4];
            unsigned long long w2[4];
            w2[0] = pack2(wa.x, wa.y); w2[1] = pack2(wa.z, wa.w);
            w2[2] = pack2(wb.x, wb.y); w2[3] = pack2(wb.z, wb.w);
            #pragma unroll
            for (int i = 0; i < 4; i++)
                #pragma unroll
                for (int j = 0; j < 4; j++)
                    acc[i][j] = ffma2(h2[i], w2[j], acc[i][j]);
        }
        __syncthreads();
    }

    // ---- epilogue: bias + relu + residual + layernorm (+ fused out-GEMM) ----
    float cbv[8], lgv[8], lbv[8];
    {
        float4 a0 = *(const float4*)(cb + c8),    a1 = *(const float4*)(cb + c8 + 4);
        float4 g0 = *(const float4*)(lg + c8),    g1 = *(const float4*)(lg + c8 + 4);
        float4 b0 = *(const float4*)(lbeta + c8), b1 = *(const float4*)(lbeta + c8 + 4);
        cbv[0]=a0.x;cbv[1]=a0.y;cbv[2]=a0.z;cbv[3]=a0.w;cbv[4]=a1.x;cbv[5]=a1.y;cbv[6]=a1.z;cbv[7]=a1.w;
        lgv[0]=g0.x;lgv[1]=g0.y;lgv[2]=g0.z;lgv[3]=g0.w;lgv[4]=g1.x;lgv[5]=g1.y;lgv[6]=g1.z;lgv[7]=g1.w;
        lbv[0]=b0.x;lbv[1]=b0.y;lbv[2]=b0.z;lbv[3]=b0.w;lbv[4]=b1.x;lbv[5]=b1.y;lbv[6]=b1.z;lbv[7]=b1.w;
    }

    #pragma unroll
    for (int i = 0; i < 4; i++) {
        int grow = row0 + rg * 4 + i;
        float hres[8];
        if (grow < n) {
            float4 r0 = *(const float4*)(g_H + grow * 64 + c8);
            float4 r1 = *(const float4*)(g_H + grow * 64 + c8 + 4);
            hres[0]=r0.x;hres[1]=r0.y;hres[2]=r0.z;hres[3]=r0.w;
            hres[4]=r1.x;hres[5]=r1.y;hres[6]=r1.z;hres[7]=r1.w;
        } else {
            #pragma unroll
            for (int u = 0; u < 8; u++) hres[u] = 0.0f;
        }
        float val[8];
        #pragma unroll
        for (int j = 0; j < 4; j++) {
            float2 a = unpack2(acc[i][j]);
            val[2*j]   = fmaxf(a.x + cbv[2*j],   0.0f) + hres[2*j];
            val[2*j+1] = fmaxf(a.y + cbv[2*j+1], 0.0f) + hres[2*j+1];
        }
        float s = 0.0f;
        #pragma unroll
        for (int u = 0; u < 8; u++) s += val[u];
        #pragma unroll
        for (int m = 1; m < 8; m <<= 1) s += __shfl_xor_sync(0xffffffffu, s, m);
        float mu = s * (1.0f / 64.0f);
        float q = 0.0f;
        #pragma unroll
        for (int u = 0; u < 8; u++) { float d = val[u] - mu; q += d * d; }
        #pragma unroll
        for (int m = 1; m < 8; m <<= 1) q += __shfl_xor_sync(0xffffffffu, q, m);
        float rs = rsqrtf(q * (1.0f / 64.0f) + LN_EPS);

        float o[8];
        #pragma unroll
        for (int u = 0; u < 8; u++)
            o[u] = (val[u] - mu) * rs * lgv[u] + lbv[u];

        if (!last) {
            if (grow < n) {
                *(float4*)(g_H + grow * 64 + c8)     = make_float4(o[0], o[1], o[2], o[3]);
                *(float4*)(g_H + grow * 64 + c8 + 4) = make_float4(o[4], o[5], o[6], o[7]);
            }
        } else {
            float4 oa = make_float4(0.f, 0.f, 0.f, 0.f);
            #pragma unroll
            for (int u = 0; u < 8; u++) {
                const float* wr = &sWout[(c8 + u) * 4];
                oa.x += o[u] * wr[0]; oa.y += o[u] * wr[1];
                oa.z += o[u] * wr[2]; oa.w += o[u] * wr[3];
            }
            #pragma unroll
            for (int m = 1; m < 8; m <<= 1) {
                oa.x += __shfl_xor_sync(0xffffffffu, oa.x, m);
                oa.y += __shfl_xor_sync(0xffffffffu, oa.y, m);
                oa.z += __shfl_xor_sync(0xffffffffu, oa.z, m);
                oa.w += __shfl_xor_sync(0xffffffffu, oa.w, m);
            }
            if ((t & 7) == 0 && grow < n) {
                oa.x += sWout[256]; oa.y += sWout[257]; oa.z += sWout[258]; oa.w += sWout[259];
                *(float4*)(out + grow * 4) = oa;
            }
        }
    }
}

// ---------------- launch ----------------
extern "C" void kernel_launch(void* const* d_in, const int* in_sizes, int n_in,
                              void* d_out, int out_size) {
    const float *x = 0, *Win = 0, *bin = 0, *chW = 0, *Wout = 0, *bout = 0;
    const float *p192[3] = {0, 0, 0};
    const int* ei = 0;
    int n192 = 0, e2 = 0, nx = 0;
    for (int i = 0; i < n_in; i++) {
        int sz = in_sizes[i];
        if      (sz == 1600000) { ei = (const int*)d_in[i]; e2 = sz; }
        else if (sz == 800000)  { x = (const float*)d_in[i]; nx = sz; }
        else if (sz == 1024)    Win  = (const float*)d_in[i];
        else if (sz == 64)      bin  = (const float*)d_in[i];
        else if (sz == 36864)   chW  = (const float*)d_in[i];
        else if (sz == 256)     Wout = (const float*)d_in[i];
        else if (sz == 4)       bout = (const float*)d_in[i];
        else if (sz == 192 && n192 < 3) p192[n192++] = (const float*)d_in[i];
    }
    const float* chb = p192[0];
    const float* lng = p192[1];
    const float* lnb = p192[2];
    float* out = (float*)d_out;

    int n = nx / 16;
    int e = e2 / 2;
    const int* src = ei;
    const int* dst = ei + e;

    static cudaStream_t s1 = 0;
    static cudaEvent_t  ev0 = 0, ev1 = 0;
    static int s_init = 0;
    if (!s_init) {
        cudaStreamCreateWithFlags(&s1, cudaStreamNonBlocking);
        cudaEventCreateWithFlags(&ev0, cudaEventDisableTiming);
        cudaEventCreateWithFlags(&ev1, cudaEventDisableTiming);
        cudaFuncSetAttribute(layer_kernel, cudaFuncAttributeMaxDynamicSharedMemorySize,
                             LK_SMEM_BYTES);
        s_init = 1;
    }

    cudaStream_t s0 = 0;
    int ingemm_blocks = (n + 31) / 32;
    int layer_blocks  = (n + 127) / 128;
    int spmm_blocks   = (n * 16 + 255) / 256;

    // fork: prepA + ingemm concurrent with CSR build (independent inputs)
    cudaEventRecord(ev0, s0);
    cudaStreamWaitEvent(s1, ev0, 0);
    prepA_kernel<<<(3 * 4096 + 255) / 256, 256, 0, s1>>>(chW);
    ingemm_kernel<<<ingemm_blocks, 256, 0, s1>>>(x, Win, bin, n);
    cudaEventRecord(ev1, s1);

    // CSR build (default stream) — counters are pre-zeroed (self-cleaning)
    count_kernel<<<(e + 255) / 256, 256, 0, s0>>>(src, dst, e);
    scan_kernel<<<1, 1024, 0, s0>>>(n);      // rowptr + dinv + counter re-zero
    scatter_kernel<<<(e + 255) / 256, 256, 0, s0>>>(src, dst, e);
    cudaStreamWaitEvent(s0, ev1, 0);

    for (int i = 0; i < 3; i++) {
        spmm_kernel<<<spmm_blocks, 256, 0, s0>>>(0, n);  // T1 = L_hat @ H
        spmm_kernel<<<spmm_blocks, 256, 0, s0>>>(1, n);  // T2 = L_hat @ T1
        layer_kernel<<<layer_blocks, 256, LK_SMEM_BYTES, s0>>>(
            i, chb + i * 64, lng + i * 64, lnb + i * 64,
            Wout, bout, out, (i == 2) ? 1 : 0, n);
    }
}

// round 8
// speedup vs baseline: 2.1535x; 1.0120x over previous
#include <cuda_runtime.h>

#define NMAX 50000
#define EMAX 800000
#define HIDDIM 64
#define LN_EPS 1e-5f
#define SCAN_CHUNK 4096
#define SCAN_NBMAX ((NMAX + SCAN_CHUNK - 1) / SCAN_CHUNK)

// ---------------- scratch (device globals; no allocation allowed) ----------------
// Counter arrays and lookback descriptors are SELF-CLEANING: zero at module
// load; count_kernel re-zeroes lookback state each launch, scan_kernel
// re-zeroes the counters after consuming them. Deterministic across replays.
__device__ __align__(16) int   g_srcdeg[NMAX];
__device__ __align__(16) int   g_rowcnt[NMAX];
__device__ __align__(16) int   g_cursor[NMAX];
__device__ __align__(16) int   g_rowptr[NMAX + 1];
__device__ __align__(16) float g_dinv[NMAX];
__device__ __align__(16) int   g_binc [SCAN_NBMAX];      // inclusive block prefixes
__device__ __align__(16) int   g_bflag[SCAN_NBMAX];      // publish flags
__device__ __align__(16) int2  g_csr[EMAX];              // {src, bitcast(w)} grouped by dst
__device__ __align__(16) float g_H [NMAX * HIDDIM];
__device__ __align__(16) float g_T1[NMAX * HIDDIM];
__device__ __align__(16) float g_T2[NMAX * HIDDIM];
__device__ __align__(16) float g_A [3 * 3 * HIDDIM * HIDDIM];  // folded weights per layer

// ---------------- f32x2 packed-FMA helpers (sm_100+ PTX) ----------------
__device__ __forceinline__ unsigned long long pack2(float a, float b) {
    unsigned long long r;
    asm("mov.b64 %0, {%1, %2};" : "=l"(r) : "f"(a), "f"(b));
    return r;
}
__device__ __forceinline__ unsigned long long ffma2(unsigned long long a,
                                                    unsigned long long b,
                                                    unsigned long long c) {
    unsigned long long d;
    asm("fma.rn.f32x2 %0, %1, %2, %3;" : "=l"(d) : "l"(a), "l"(b), "l"(c));
    return d;
}
__device__ __forceinline__ float2 unpack2(unsigned long long v) {
    float2 f;
    asm("mov.b64 {%0, %1}, %2;" : "=f"(f.x), "=f"(f.y) : "l"(v));
    return f;
}

// ---------------- weight folding: A0 = W0 - W2, A1 = W1, A2 = 2*W2 ----------------
__global__ void prepA_kernel(const float* __restrict__ W) {
    int idx = blockIdx.x * blockDim.x + threadIdx.x;
    if (idx < 3 * 4096) {
        int i = idx >> 12, r = idx & 4095;
        const float* Wi = W + i * 3 * 4096;
        float w0 = Wi[r], w1 = Wi[4096 + r], w2 = Wi[8192 + r];
        float* Ai = g_A + i * 3 * 4096;
        Ai[r]        = w0 - w2;
        Ai[4096 + r] = w1;
        Ai[8192 + r] = 2.0f * w2;
    }
}

// scalar, 1 edge/thread (measured fastest); also resets lookback descriptors
__global__ void count_kernel(const int* __restrict__ src, const int* __restrict__ dst, int e) {
    int i = blockIdx.x * blockDim.x + threadIdx.x;
    if (i < SCAN_NBMAX) { g_bflag[i] = 0; g_binc[i] = 0; }
    if (i < e) {
        atomicAdd(&g_srcdeg[src[i]], 1);
        atomicAdd(&g_rowcnt[dst[i]], 1);
    }
}

// ---------------- decoupled-lookback scan: rowcnt -> rowptr (exclusive) --------
// Also: srcdeg -> dinv, and zero srcdeg/rowcnt/cursor for the next launch.
// grid = ceil(n/4096) blocks x 1024 threads; int4 per thread.
__global__ __launch_bounds__(1024) void scan_kernel(int n) {
    __shared__ int warp_tot[32];
    __shared__ int s_prev;
    int b = blockIdx.x, t = threadIdx.x, lane = t & 31, wid = t >> 5;
    int i = b * SCAN_CHUNK + t * 4;
    const int4 zero4 = make_int4(0, 0, 0, 0);

    int4 v = zero4;
    bool act = (i + 3) < n;   // n is a multiple of 4 in practice; tail handled below
    if (act) {
        v = *(const int4*)(g_rowcnt + i);
        *(int4*)(g_rowcnt + i) = zero4;
        int4 dg = *(const int4*)(g_srcdeg + i);
        *(int4*)(g_srcdeg + i) = zero4;
        *(int4*)(g_cursor + i) = zero4;
        float4 dv;
        dv.x = (dg.x > 0) ? rsqrtf((float)dg.x) : 0.0f;
        dv.y = (dg.y > 0) ? rsqrtf((float)dg.y) : 0.0f;
        dv.z = (dg.z > 0) ? rsqrtf((float)dg.z) : 0.0f;
        dv.w = (dg.w > 0) ? rsqrtf((float)dg.w) : 0.0f;
        *(float4*)(g_dinv + i) = dv;
    } else {
        // scalar tail (only in the last block, only if n % 4 != 0 region)
        for (int q = 0; q < 4; q++) {
            int ii = i + q;
            if (ii < n) {
                int c = g_rowcnt[ii]; g_rowcnt[ii] = 0;
                ((int*)&v)[q] = c;
                int d = g_srcdeg[ii]; g_srcdeg[ii] = 0;
                g_cursor[ii] = 0;
                g_dinv[ii] = (d > 0) ? rsqrtf((float)d) : 0.0f;
            }
        }
    }

    int tsum = v.x + v.y + v.z + v.w;
    int x = tsum;
    #pragma unroll
    for (int off = 1; off < 32; off <<= 1) {
        int y = __shfl_up_sync(0xffffffffu, x, off);
        if (lane >= off) x += y;
    }
    if (lane == 31) warp_tot[wid] = x;
    __syncthreads();
    if (wid == 0) {
        int wt = warp_tot[lane];
        #pragma unroll
        for (int off = 1; off < 32; off <<= 1) {
            int y = __shfl_up_sync(0xffffffffu, wt, off);
            if (lane >= off) wt += y;
        }
        warp_tot[lane] = wt;
    }
    __syncthreads();
    int wp = (wid > 0) ? warp_tot[wid - 1] : 0;
    int excl_local = wp + (x - tsum);       // exclusive prefix within block
    int block_total = warp_tot[31];

    // lookback: thread 0 waits for predecessor's inclusive prefix
    if (t == 0) {
        int prev = 0;
        if (b > 0) {
            while (atomicAdd(&g_bflag[b - 1], 0) == 0) {}
            __threadfence();
            prev = atomicAdd(&g_binc[b - 1], 0);
        }
        atomicExch(&g_binc[b], prev + block_total);
        __threadfence();
        atomicExch(&g_bflag[b], 1);
        s_prev = prev;
        if (b == gridDim.x - 1) g_rowptr[n] = prev + block_total;
    }
    __syncthreads();
    int base = s_prev + excl_local;

    if (act) {
        int4 rp;
        rp.x = base;
        rp.y = base + v.x;
        rp.z = base + v.x + v.y;
        rp.w = base + v.x + v.y + v.z;
        *(int4*)(g_rowptr + i) = rp;
    } else {
        int c = base;
        for (int q = 0; q < 4; q++) {
            int ii = i + q;
            if (ii < n) { g_rowptr[ii] = c; c += ((int*)&v)[q]; }
        }
    }
}

__global__ void scatter_kernel(const int* __restrict__ src, const int* __restrict__ dst, int e) {
    int i = blockIdx.x * blockDim.x + threadIdx.x;
    if (i < e) {
        int s = src[i], d = dst[i];
        float w = -g_dinv[s] * g_dinv[d];
        int pos = g_rowptr[d] + atomicAdd(&g_cursor[d], 1);
        g_csr[pos] = make_int2(s, __float_as_int(w));
    }
}

// ---------------- SpMM: Y[dst] = sum_e w * X[src]  (16 threads per row) ----------------
__global__ __launch_bounds__(256) void spmm_kernel(int mode, int n) {
    const float* __restrict__ X = mode ? g_T1 : g_H;
    float* __restrict__ Y       = mode ? g_T2 : g_T1;
    int gid  = blockIdx.x * blockDim.x + threadIdx.x;
    int row  = gid >> 4;
    int lane = gid & 15;
    if (row >= n) return;
    int beg = g_rowptr[row], end = g_rowptr[row + 1];
    float4 a0 = make_float4(0.f, 0.f, 0.f, 0.f);
    float4 a1 = make_float4(0.f, 0.f, 0.f, 0.f);
    int e = beg;
    for (; e + 2 <= end; e += 2) {
        int2 c0 = g_csr[e];
        int2 c1 = g_csr[e + 1];
        float4 v0 = *(const float4*)(X + c0.x * HIDDIM + lane * 4);
        float4 v1 = *(const float4*)(X + c1.x * HIDDIM + lane * 4);
        float w0 = __int_as_float(c0.y), w1 = __int_as_float(c1.y);
        a0.x += w0 * v0.x; a0.y += w0 * v0.y; a0.z += w0 * v0.z; a0.w += w0 * v0.w;
        a1.x += w1 * v1.x; a1.y += w1 * v1.y; a1.z += w1 * v1.z; a1.w += w1 * v1.w;
    }
    if (e < end) {
        int2 c0 = g_csr[e];
        float4 v0 = *(const float4*)(X + c0.x * HIDDIM + lane * 4);
        float w0 = __int_as_float(c0.y);
        a0.x += w0 * v0.x; a0.y += w0 * v0.y; a0.z += w0 * v0.z; a0.w += w0 * v0.w;
    }
    float4 r;
    r.x = a0.x + a1.x; r.y = a0.y + a1.y; r.z = a0.z + a1.z; r.w = a0.w + a1.w;
    *(float4*)(Y + row * HIDDIM + lane * 4) = r;
}

// ---------------- input GEMM: g_H = x @ W_in + b_in ----------------
__global__ __launch_bounds__(256) void ingemm_kernel(const float* __restrict__ x,
                                                     const float* __restrict__ Win,
                                                     const float* __restrict__ bin, int n) {
    __shared__ float sW[16 * 64];
    __shared__ float xt[16 * 33];
    __shared__ float so[32 * 65];
    int t = threadIdx.x, lane = t & 31, wg = t >> 5;
    int row0 = blockIdx.x * 32;
    for (int idx = t; idx < 1024; idx += 256) sW[idx] = Win[idx];
    for (int idx = t; idx < 512; idx += 256) {
        int r = idx >> 4, k = idx & 15;
        int row = row0 + r;
        xt[k * 33 + r] = (row < n) ? x[row * 16 + k] : 0.0f;
    }
    __syncthreads();
    float acc[8] = {0, 0, 0, 0, 0, 0, 0, 0};
    #pragma unroll
    for (int k = 0; k < 16; k++) {
        float xv = xt[k * 33 + lane];
        float4 w0 = *(const float4*)&sW[k * 64 + wg * 8];
        float4 w1 = *(const float4*)&sW[k * 64 + wg * 8 + 4];
        acc[0] += xv * w0.x; acc[1] += xv * w0.y; acc[2] += xv * w0.z; acc[3] += xv * w0.w;
        acc[4] += xv * w1.x; acc[5] += xv * w1.y; acc[6] += xv * w1.z; acc[7] += xv * w1.w;
    }
    #pragma unroll
    for (int u = 0; u < 8; u++) {
        int j = wg * 8 + u;
        so[lane * 65 + j] = acc[u] + bin[j];
    }
    __syncthreads();
    int r = t >> 3, c = (t & 7) * 8;
    int row = row0 + r;
    if (row < n) {
        float4 v0, v1;
        v0.x = so[r*65+c+0]; v0.y = so[r*65+c+1]; v0.z = so[r*65+c+2]; v0.w = so[r*65+c+3];
        v1.x = so[r*65+c+4]; v1.y = so[r*65+c+5]; v1.z = so[r*65+c+6]; v1.w = so[r*65+c+7];
        *(float4*)(g_H + row * 64 + c)     = v0;
        *(float4*)(g_H + row * 64 + c + 4) = v1;
    }
}

// ---------------- fused layer (128 rows/block, f32x2 FMA, fused out-GEMM on last) ----
#define LK_HT_STRIDE 129
#define LK_HT_FLOATS (64 * LK_HT_STRIDE)          // 8256
#define LK_SMEM_BYTES ((LK_HT_FLOATS + 4096) * 4) // 49408

__global__ __launch_bounds__(256) void layer_kernel(int layer,
                                                    const float* __restrict__ cb,
                                                    const float* __restrict__ lg,
                                                    const float* __restrict__ lbeta,
                                                    const float* __restrict__ Wout,
                                                    const float* __restrict__ bout,
                                                    float* __restrict__ out,
                                                    int last, int n) {
    extern __shared__ float smem[];
    float* ht = smem;                 // [64][129] transposed tile
    float* sA = smem + LK_HT_FLOATS;  // [64][64] current weight matrix
    __shared__ float sWout[260];

    int t = threadIdx.x;
    int c8 = (t & 7) * 8;             // column group (8 cols)
    int rg = t >> 3;                  // row group (4 rows)
    int row0 = blockIdx.x * 128;
    const float* __restrict__ A = g_A + layer * 12288;

    if (last) {
        sWout[t] = Wout[t];
        if (t < 4) sWout[256 + t] = bout[t];
    }

    unsigned long long acc[4][4];
    #pragma unroll
    for (int i = 0; i < 4; i++)
        #pragma unroll
        for (int j = 0; j < 4; j++) acc[i][j] = pack2(0.0f, 0.0f);

    #pragma unroll
    for (int pass = 0; pass < 3; pass++) {
        const float* __restrict__ S = (pass == 0) ? g_H : ((pass == 1) ? g_T1 : g_T2);
        for (int idx = t; idx < 1024; idx += 256)
            ((float4*)sA)[idx] = ((const float4*)(A + pass * 4096))[idx];
        for (int idx = t; idx < 2048; idx += 256) {
            int r = idx >> 4, k4 = (idx & 15) * 4;
            int grow = row0 + r;
            float4 v = make_float4(0.f, 0.f, 0.f, 0.f);
            if (grow < n) v = *(const float4*)(S + grow * 64 + k4);
            int b = k4 * LK_HT_STRIDE + r;
            ht[b]                    = v.x;
            ht[b + LK_HT_STRIDE]     = v.y;
            ht[b + 2 * LK_HT_STRIDE] = v.z;
            ht[b + 3 * LK_HT_STRIDE] = v.w;
        }
        __syncthreads();
        #pragma unroll 8
        for (int k = 0; k < 64; k++) {
            unsigned long long h2[4];
            #pragma unroll
            for (int i = 0; i < 4; i++) {
                float hv = ht[k * LK_HT_STRIDE + rg * 4 + i];
                h2[i] = pack2(hv, hv);
            }
            float4 wa = *(const float4*)&sA[k * 64 + c8];
            float4 wb = *(const float4*)&sA[k * 64 + c8 + 4];
            unsigned long long w2[4];
            w2[0] = pack2(wa.x, wa.y); w2[1] = pack2(wa.z, wa.w);
            w2[2] = pack2(wb.x, wb.y); w2[3] = pack2(wb.z, wb.w);
            #pragma unroll
            for (int i = 0; i < 4; i++)
                #pragma unroll
                for (int j = 0; j < 4; j++)
                    acc[i][j] = ffma2(h2[i], w2[j], acc[i][j]);
        }
        __syncthreads();
    }

    // ---- epilogue: bias + relu + residual + layernorm (+ fused out-GEMM) ----
    float cbv[8], lgv[8], lbv[8];
    {
        float4 a0 = *(const float4*)(cb + c8),    a1 = *(const float4*)(cb + c8 + 4);
        float4 g0 = *(const float4*)(lg + c8),    g1 = *(const float4*)(lg + c8 + 4);
        float4 b0 = *(const float4*)(lbeta + c8), b1 = *(const float4*)(lbeta + c8 + 4);
        cbv[0]=a0.x;cbv[1]=a0.y;cbv[2]=a0.z;cbv[3]=a0.w;cbv[4]=a1.x;cbv[5]=a1.y;cbv[6]=a1.z;cbv[7]=a1.w;
        lgv[0]=g0.x;lgv[1]=g0.y;lgv[2]=g0.z;lgv[3]=g0.w;lgv[4]=g1.x;lgv[5]=g1.y;lgv[6]=g1.z;lgv[7]=g1.w;
        lbv[0]=b0.x;lbv[1]=b0.y;lbv[2]=b0.z;lbv[3]=b0.w;lbv[4]=b1.x;lbv[5]=b1.y;lbv[6]=b1.z;lbv[7]=b1.w;
    }

    #pragma unroll
    for (int i = 0; i < 4; i++) {
        int grow = row0 + rg * 4 + i;
        float hres[8];
        if (grow < n) {
            float4 r0 = *(const float4*)(g_H + grow * 64 + c8);
            float4 r1 = *(const float4*)(g_H + grow * 64 + c8 + 4);
            hres[0]=r0.x;hres[1]=r0.y;hres[2]=r0.z;hres[3]=r0.w;
            hres[4]=r1.x;hres[5]=r1.y;hres[6]=r1.z;hres[7]=r1.w;
        } else {
            #pragma unroll
            for (int u = 0; u < 8; u++) hres[u] = 0.0f;
        }
        float val[8];
        #pragma unroll
        for (int j = 0; j < 4; j++) {
            float2 a = unpack2(acc[i][j]);
            val[2*j]   = fmaxf(a.x + cbv[2*j],   0.0f) + hres[2*j];
            val[2*j+1] = fmaxf(a.y + cbv[2*j+1], 0.0f) + hres[2*j+1];
        }
        float s = 0.0f;
        #pragma unroll
        for (int u = 0; u < 8; u++) s += val[u];
        #pragma unroll
        for (int m = 1; m < 8; m <<= 1) s += __shfl_xor_sync(0xffffffffu, s, m);
        float mu = s * (1.0f / 64.0f);
        float q = 0.0f;
        #pragma unroll
        for (int u = 0; u < 8; u++) { float d = val[u] - mu; q += d * d; }
        #pragma unroll
        for (int m = 1; m < 8; m <<= 1) q += __shfl_xor_sync(0xffffffffu, q, m);
        float rs = rsqrtf(q * (1.0f / 64.0f) + LN_EPS);

        float o[8];
        #pragma unroll
        for (int u = 0; u < 8; u++)
            o[u] = (val[u] - mu) * rs * lgv[u] + lbv[u];

        if (!last) {
            if (grow < n) {
                *(float4*)(g_H + grow * 64 + c8)     = make_float4(o[0], o[1], o[2], o[3]);
                *(float4*)(g_H + grow * 64 + c8 + 4) = make_float4(o[4], o[5], o[6], o[7]);
            }
        } else {
            float4 oa = make_float4(0.f, 0.f, 0.f, 0.f);
            #pragma unroll
            for (int u = 0; u < 8; u++) {
                const float* wr = &sWout[(c8 + u) * 4];
                oa.x += o[u] * wr[0]; oa.y += o[u] * wr[1];
                oa.z += o[u] * wr[2]; oa.w += o[u] * wr[3];
            }
            #pragma unroll
            for (int m = 1; m < 8; m <<= 1) {
                oa.x += __shfl_xor_sync(0xffffffffu, oa.x, m);
                oa.y += __shfl_xor_sync(0xffffffffu, oa.y, m);
                oa.z += __shfl_xor_sync(0xffffffffu, oa.z, m);
                oa.w += __shfl_xor_sync(0xffffffffu, oa.w, m);
            }
            if ((t & 7) == 0 && grow < n) {
                oa.x += sWout[256]; oa.y += sWout[257]; oa.z += sWout[258]; oa.w += sWout[259];
                *(float4*)(out + grow * 4) = oa;
            }
        }
    }
}

// ---------------- launch ----------------
extern "C" void kernel_launch(void* const* d_in, const int* in_sizes, int n_in,
                              void* d_out, int out_size) {
    const float *x = 0, *Win = 0, *bin = 0, *chW = 0, *Wout = 0, *bout = 0;
    const float *p192[3] = {0, 0, 0};
    const int* ei = 0;
    int n192 = 0, e2 = 0, nx = 0;
    for (int i = 0; i < n_in; i++) {
        int sz = in_sizes[i];
        if      (sz == 1600000) { ei = (const int*)d_in[i]; e2 = sz; }
        else if (sz == 800000)  { x = (const float*)d_in[i]; nx = sz; }
        else if (sz == 1024)    Win  = (const float*)d_in[i];
        else if (sz == 64)      bin  = (const float*)d_in[i];
        else if (sz == 36864)   chW  = (const float*)d_in[i];
        else if (sz == 256)     Wout = (const float*)d_in[i];
        else if (sz == 4)       bout = (const float*)d_in[i];
        else if (sz == 192 && n192 < 3) p192[n192++] = (const float*)d_in[i];
    }
    const float* chb = p192[0];
    const float* lng = p192[1];
    const float* lnb = p192[2];
    float* out = (float*)d_out;

    int n = nx / 16;
    int e = e2 / 2;
    const int* src = ei;
    const int* dst = ei + e;

    static cudaStream_t s1 = 0;
    static cudaEvent_t  ev0 = 0, ev1 = 0;
    static int s_init = 0;
    if (!s_init) {
        cudaStreamCreateWithFlags(&s1, cudaStreamNonBlocking);
        cudaEventCreateWithFlags(&ev0, cudaEventDisableTiming);
        cudaEventCreateWithFlags(&ev1, cudaEventDisableTiming);
        cudaFuncSetAttribute(layer_kernel, cudaFuncAttributeMaxDynamicSharedMemorySize,
                             LK_SMEM_BYTES);
        s_init = 1;
    }

    cudaStream_t s0 = 0;
    int ingemm_blocks = (n + 31) / 32;
    int layer_blocks  = (n + 127) / 128;
    int spmm_blocks   = (n * 16 + 255) / 256;
    int scan_blocks   = (n + SCAN_CHUNK - 1) / SCAN_CHUNK;

    // fork: prepA + ingemm concurrent with CSR build (independent inputs)
    cudaEventRecord(ev0, s0);
    cudaStreamWaitEvent(s1, ev0, 0);
    prepA_kernel<<<(3 * 4096 + 255) / 256, 256, 0, s1>>>(chW);
    ingemm_kernel<<<ingemm_blocks, 256, 0, s1>>>(x, Win, bin, n);
    cudaEventRecord(ev1, s1);

    // CSR build (default stream) — counters pre-zeroed (self-cleaning)
    count_kernel<<<(e + 255) / 256, 256, 0, s0>>>(src, dst, e);
    scan_kernel<<<scan_blocks, 1024, 0, s0>>>(n);  // lookback scan + dinv + re-zero
    scatter_kernel<<<(e + 255) / 256, 256, 0, s0>>>(src, dst, e);
    cudaStreamWaitEvent(s0, ev1, 0);

    for (int i = 0; i < 3; i++) {
        spmm_kernel<<<spmm_blocks, 256, 0, s0>>>(0, n);  // T1 = L_hat @ H
        spmm_kernel<<<spmm_blocks, 256, 0, s0>>>(1, n);  // T2 = L_hat @ T1
        layer_kernel<<<layer_blocks, 256, LK_SMEM_BYTES, s0>>>(
            i, chb + i * 64, lng + i * 64, lnb + i * 64,
            Wout, bout, out, (i == 2) ? 1 : 0, n);
    }
}

// round 9
// speedup vs baseline: 2.2487x; 1.0442x over previous
#include <cuda_runtime.h>

#define NMAX 50000
#define EMAX 800000
#define HIDDIM 64
#define LN_EPS 1e-5f
#define SCAN_CHUNK 4096

// ---------------- scratch (device globals; no allocation allowed) ----------------
// Self-cleaning counters: zero at module load; scan_kernel zeroes srcdeg/cursor
// (own chunk), scatter_kernel zeroes rowcnt. Deterministic across graph replays.
__device__ __align__(16) int   g_srcdeg[NMAX];
__device__ __align__(16) int   g_rowcnt[NMAX];
__device__ __align__(16) int   g_cursor[NMAX];
__device__ __align__(16) int   g_rowptr[NMAX + 1];
__device__ __align__(16) float g_dinv[NMAX];
__device__ __align__(16) int2  g_csr[EMAX];              // {src, bitcast(w)} grouped by dst
__device__ __align__(16) float g_H [NMAX * HIDDIM];
__device__ __align__(16) float g_T1[NMAX * HIDDIM];
__device__ __align__(16) float g_T2[NMAX * HIDDIM];
__device__ __align__(16) float g_A [3 * 3 * HIDDIM * HIDDIM];  // folded weights per layer

// ---------------- f32x2 packed-FMA helpers (sm_100+ PTX) ----------------
__device__ __forceinline__ unsigned long long pack2(float a, float b) {
    unsigned long long r;
    asm("mov.b64 %0, {%1, %2};" : "=l"(r) : "f"(a), "f"(b));
    return r;
}
__device__ __forceinline__ unsigned long long ffma2(unsigned long long a,
                                                    unsigned long long b,
                                                    unsigned long long c) {
    unsigned long long d;
    asm("fma.rn.f32x2 %0, %1, %2, %3;" : "=l"(d) : "l"(a), "l"(b), "l"(c));
    return d;
}
__device__ __forceinline__ float2 unpack2(unsigned long long v) {
    float2 f;
    asm("mov.b64 {%0, %1}, %2;" : "=f"(f.x), "=f"(f.y) : "l"(v));
    return f;
}

// ---------------- weight folding: A0 = W0 - W2, A1 = W1, A2 = 2*W2 ----------------
__global__ void prepA_kernel(const float* __restrict__ W) {
    int idx = blockIdx.x * blockDim.x + threadIdx.x;
    if (idx < 3 * 4096) {
        int i = idx >> 12, r = idx & 4095;
        const float* Wi = W + i * 3 * 4096;
        float w0 = Wi[r], w1 = Wi[4096 + r], w2 = Wi[8192 + r];
        float* Ai = g_A + i * 3 * 4096;
        Ai[r]        = w0 - w2;
        Ai[4096 + r] = w1;
        Ai[8192 + r] = 2.0f * w2;
    }
}

// scalar, 1 edge/thread (measured fastest across rounds)
__global__ void count_kernel(const int* __restrict__ src, const int* __restrict__ dst, int e) {
    int i = blockIdx.x * blockDim.x + threadIdx.x;
    if (i < e) {
        atomicAdd(&g_srcdeg[src[i]], 1);
        atomicAdd(&g_rowcnt[dst[i]], 1);
    }
}

// ---------------- communication-free scan: rowcnt -> rowptr (exclusive) --------
// 13 chunks only: each block recomputes its prefix by reducing ALL predecessor
// chunks directly (max 48 ints/thread) — no lookback chain, no spinning.
// Also: srcdeg -> dinv, zero srcdeg/cursor (own chunk). rowcnt NOT zeroed here
// (foreign blocks read it); scatter_kernel zeroes it.
__global__ __launch_bounds__(1024) void scan_kernel(int n) {
    __shared__ int warp_tot[32];
    __shared__ int warp_sum[32];
    __shared__ int s_prev;
    int b = blockIdx.x, t = threadIdx.x, lane = t & 31, wid = t >> 5;
    int i = b * SCAN_CHUNK + t * 4;
    const int4 zero4 = make_int4(0, 0, 0, 0);

    // ---- local chunk: load counts, produce dinv, zero own srcdeg/cursor ----
    int4 v = zero4;
    bool act = (i + 3) < n;
    if (act) {
        v = *(const int4*)(g_rowcnt + i);
        int4 dg = *(const int4*)(g_srcdeg + i);
        *(int4*)(g_srcdeg + i) = zero4;
        *(int4*)(g_cursor + i) = zero4;
        float4 dv;
        dv.x = (dg.x > 0) ? rsqrtf((float)dg.x) : 0.0f;
        dv.y = (dg.y > 0) ? rsqrtf((float)dg.y) : 0.0f;
        dv.z = (dg.z > 0) ? rsqrtf((float)dg.z) : 0.0f;
        dv.w = (dg.w > 0) ? rsqrtf((float)dg.w) : 0.0f;
        *(float4*)(g_dinv + i) = dv;
    } else {
        for (int q = 0; q < 4; q++) {
            int ii = i + q;
            if (ii < n) {
                ((int*)&v)[q] = g_rowcnt[ii];
                int d = g_srcdeg[ii]; g_srcdeg[ii] = 0;
                g_cursor[ii] = 0;
                g_dinv[ii] = (d > 0) ? rsqrtf((float)d) : 0.0f;
            }
        }
    }

    // ---- prefix over predecessor chunks: direct parallel reduction ----
    int psum = 0;
    int m = b * SCAN_CHUNK;           // multiple of 4; fully < n for all b
    for (int j = t * 4; j < m; j += 4096) {
        int4 c = *(const int4*)(g_rowcnt + j);
        psum += c.x + c.y + c.z + c.w;
    }
    #pragma unroll
    for (int off = 16; off > 0; off >>= 1)
        psum += __shfl_xor_sync(0xffffffffu, psum, off);
    if (lane == 0) warp_sum[wid] = psum;

    // ---- local exclusive scan ----
    int tsum = v.x + v.y + v.z + v.w;
    int x = tsum;
    #pragma unroll
    for (int off = 1; off < 32; off <<= 1) {
        int y = __shfl_up_sync(0xffffffffu, x, off);
        if (lane >= off) x += y;
    }
    if (lane == 31) warp_tot[wid] = x;
    __syncthreads();
    if (wid == 0) {
        int wt = warp_tot[lane];
        #pragma unroll
        for (int off = 1; off < 32; off <<= 1) {
            int y = __shfl_up_sync(0xffffffffu, wt, off);
            if (lane >= off) wt += y;
        }
        warp_tot[lane] = wt;
        // reduce warp_sum (32 values) in the same warp
        int p = warp_sum[lane];
        #pragma unroll
        for (int off = 16; off > 0; off >>= 1)
            p += __shfl_xor_sync(0xffffffffu, p, off);
        if (lane == 0) s_prev = p;
    }
    __syncthreads();
    int wp = (wid > 0) ? warp_tot[wid - 1] : 0;
    int base = s_prev + wp + (x - tsum);

    if (act) {
        int4 rp;
        rp.x = base;
        rp.y = base + v.x;
        rp.z = base + v.x + v.y;
        rp.w = base + v.x + v.y + v.z;
        *(int4*)(g_rowptr + i) = rp;
    } else {
        int c = base;
        for (int q = 0; q < 4; q++) {
            int ii = i + q;
            if (ii < n) { g_rowptr[ii] = c; c += ((int*)&v)[q]; }
        }
    }
    if (b == gridDim.x - 1 && t == 1023)
        g_rowptr[n] = s_prev + warp_tot[31];
}

// scatter + deferred rowcnt re-zero (rowcnt is not read here)
__global__ void scatter_kernel(const int* __restrict__ src, const int* __restrict__ dst,
                               int e, int n) {
    int i = blockIdx.x * blockDim.x + threadIdx.x;
    if (i < n) g_rowcnt[i] = 0;
    if (i < e) {
        int s = src[i], d = dst[i];
        float w = -g_dinv[s] * g_dinv[d];
        int pos = g_rowptr[d] + atomicAdd(&g_cursor[d], 1);
        g_csr[pos] = make_int2(s, __float_as_int(w));
    }
}

// ---------------- SpMM: Y[dst] = sum_e w * X[src]  (16 threads per row) ----------------
__global__ __launch_bounds__(256) void spmm_kernel(int mode, int n) {
    const float* __restrict__ X = mode ? g_T1 : g_H;
    float* __restrict__ Y       = mode ? g_T2 : g_T1;
    int gid  = blockIdx.x * blockDim.x + threadIdx.x;
    int row  = gid >> 4;
    int lane = gid & 15;
    if (row >= n) return;
    int beg = g_rowptr[row], end = g_rowptr[row + 1];
    float4 a0 = make_float4(0.f, 0.f, 0.f, 0.f);
    float4 a1 = make_float4(0.f, 0.f, 0.f, 0.f);
    int e = beg;
    for (; e + 2 <= end; e += 2) {
        int2 c0 = g_csr[e];
        int2 c1 = g_csr[e + 1];
        float4 v0 = *(const float4*)(X + c0.x * HIDDIM + lane * 4);
        float4 v1 = *(const float4*)(X + c1.x * HIDDIM + lane * 4);
        float w0 = __int_as_float(c0.y), w1 = __int_as_float(c1.y);
        a0.x += w0 * v0.x; a0.y += w0 * v0.y; a0.z += w0 * v0.z; a0.w += w0 * v0.w;
        a1.x += w1 * v1.x; a1.y += w1 * v1.y; a1.z += w1 * v1.z; a1.w += w1 * v1.w;
    }
    if (e < end) {
        int2 c0 = g_csr[e];
        float4 v0 = *(const float4*)(X + c0.x * HIDDIM + lane * 4);
        float w0 = __int_as_float(c0.y);
        a0.x += w0 * v0.x; a0.y += w0 * v0.y; a0.z += w0 * v0.z; a0.w += w0 * v0.w;
    }
    float4 r;
    r.x = a0.x + a1.x; r.y = a0.y + a1.y; r.z = a0.z + a1.z; r.w = a0.w + a1.w;
    *(float4*)(Y + row * HIDDIM + lane * 4) = r;
}

// ---------------- input GEMM: g_H = x @ W_in + b_in ----------------
__global__ __launch_bounds__(256) void ingemm_kernel(const float* __restrict__ x,
                                                     const float* __restrict__ Win,
                                                     const float* __restrict__ bin, int n) {
    __shared__ float sW[16 * 64];
    __shared__ float xt[16 * 33];
    __shared__ float so[32 * 65];
    int t = threadIdx.x, lane = t & 31, wg = t >> 5;
    int row0 = blockIdx.x * 32;
    for (int idx = t; idx < 1024; idx += 256) sW[idx] = Win[idx];
    for (int idx = t; idx < 512; idx += 256) {
        int r = idx >> 4, k = idx & 15;
        int row = row0 + r;
        xt[k * 33 + r] = (row < n) ? x[row * 16 + k] : 0.0f;
    }
    __syncthreads();
    float acc[8] = {0, 0, 0, 0, 0, 0, 0, 0};
    #pragma unroll
    for (int k = 0; k < 16; k++) {
        float xv = xt[k * 33 + lane];
        float4 w0 = *(const float4*)&sW[k * 64 + wg * 8];
        float4 w1 = *(const float4*)&sW[k * 64 + wg * 8 + 4];
        acc[0] += xv * w0.x; acc[1] += xv * w0.y; acc[2] += xv * w0.z; acc[3] += xv * w0.w;
        acc[4] += xv * w1.x; acc[5] += xv * w1.y; acc[6] += xv * w1.z; acc[7] += xv * w1.w;
    }
    #pragma unroll
    for (int u = 0; u < 8; u++) {
        int j = wg * 8 + u;
        so[lane * 65 + j] = acc[u] + bin[j];
    }
    __syncthreads();
    int r = t >> 3, c = (t & 7) * 8;
    int row = row0 + r;
    if (row < n) {
        float4 v0, v1;
        v0.x = so[r*65+c+0]; v0.y = so[r*65+c+1]; v0.z = so[r*65+c+2]; v0.w = so[r*65+c+3];
        v1.x = so[r*65+c+4]; v1.y = so[r*65+c+5]; v1.z = so[r*65+c+6]; v1.w = so[r*65+c+7];
        *(float4*)(g_H + row * 64 + c)     = v0;
        *(float4*)(g_H + row * 64 + c + 4) = v1;
    }
}

// ---------------- fused layer (128 rows/block, f32x2 FMA, fused out-GEMM on last) ----
#define LK_HT_STRIDE 129
#define LK_HT_FLOATS (64 * LK_HT_STRIDE)          // 8256
#define LK_SMEM_BYTES ((LK_HT_FLOATS + 4096) * 4) // 49408

__global__ __launch_bounds__(256) void layer_kernel(int layer,
                                                    const float* __restrict__ cb,
                                                    const float* __restrict__ lg,
                                                    const float* __restrict__ lbeta,
                                                    const float* __restrict__ Wout,
                                                    const float* __restrict__ bout,
                                                    float* __restrict__ out,
                                                    int last, int n) {
    extern __shared__ float smem[];
    float* ht = smem;                 // [64][129] transposed tile
    float* sA = smem + LK_HT_FLOATS;  // [64][64] current weight matrix
    __shared__ float sWout[260];

    int t = threadIdx.x;
    int c8 = (t & 7) * 8;             // column group (8 cols)
    int rg = t >> 3;                  // row group (4 rows)
    int row0 = blockIdx.x * 128;
    const float* __restrict__ A = g_A + layer * 12288;

    if (last) {
        sWout[t] = Wout[t];
        if (t < 4) sWout[256 + t] = bout[t];
    }

    unsigned long long acc[4][4];
    #pragma unroll
    for (int i = 0; i < 4; i++)
        #pragma unroll
        for (int j = 0; j < 4; j++) acc[i][j] = pack2(0.0f, 0.0f);

    #pragma unroll
    for (int pass = 0; pass < 3; pass++) {
        const float* __restrict__ S = (pass == 0) ? g_H : ((pass == 1) ? g_T1 : g_T2);
        for (int idx = t; idx < 1024; idx += 256)
            ((float4*)sA)[idx] = ((const float4*)(A + pass * 4096))[idx];
        for (int idx = t; idx < 2048; idx += 256) {
            int r = idx >> 4, k4 = (idx & 15) * 4;
            int grow = row0 + r;
            float4 v = make_float4(0.f, 0.f, 0.f, 0.f);
            if (grow < n) v = *(const float4*)(S + grow * 64 + k4);
            int b = k4 * LK_HT_STRIDE + r;
            ht[b]                    = v.x;
            ht[b + LK_HT_STRIDE]     = v.y;
            ht[b + 2 * LK_HT_STRIDE] = v.z;
            ht[b + 3 * LK_HT_STRIDE] = v.w;
        }
        __syncthreads();
        #pragma unroll 8
        for (int k = 0; k < 64; k++) {
            unsigned long long h2[4];
            #pragma unroll
            for (int i = 0; i < 4; i++) {
                float hv = ht[k * LK_HT_STRIDE + rg * 4 + i];
                h2[i] = pack2(hv, hv);
            }
            float4 wa = *(const float4*)&sA[k * 64 + c8];
            float4 wb = *(const float4*)&sA[k * 64 + c8 + 4];
            unsigned long long w2[4];
            w2[0] = pack2(wa.x, wa.y); w2[1] = pack2(wa.z, wa.w);
            w2[2] = pack2(wb.x, wb.y); w2[3] = pack2(wb.z, wb.w);
            #pragma unroll
            for (int i = 0; i < 4; i++)
                #pragma unroll
                for (int j = 0; j < 4; j++)
                    acc[i][j] = ffma2(h2[i], w2[j], acc[i][j]);
        }
        __syncthreads();
    }

    // ---- epilogue: bias + relu + residual + layernorm (+ fused out-GEMM) ----
    float cbv[8], lgv[8], lbv[8];
    {
        float4 a0 = *(const float4*)(cb + c8),    a1 = *(const float4*)(cb + c8 + 4);
        float4 g0 = *(const float4*)(lg + c8),    g1 = *(const float4*)(lg + c8 + 4);
        float4 b0 = *(const float4*)(lbeta + c8), b1 = *(const float4*)(lbeta + c8 + 4);
        cbv[0]=a0.x;cbv[1]=a0.y;cbv[2]=a0.z;cbv[3]=a0.w;cbv[4]=a1.x;cbv[5]=a1.y;cbv[6]=a1.z;cbv[7]=a1.w;
        lgv[0]=g0.x;lgv[1]=g0.y;lgv[2]=g0.z;lgv[3]=g0.w;lgv[4]=g1.x;lgv[5]=g1.y;lgv[6]=g1.z;lgv[7]=g1.w;
        lbv[0]=b0.x;lbv[1]=b0.y;lbv[2]=b0.z;lbv[3]=b0.w;lbv[4]=b1.x;lbv[5]=b1.y;lbv[6]=b1.z;lbv[7]=b1.w;
    }

    #pragma unroll
    for (int i = 0; i < 4; i++) {
        int grow = row0 + rg * 4 + i;
        float hres[8];
        if (grow < n) {
            float4 r0 = *(const float4*)(g_H + grow * 64 + c8);
            float4 r1 = *(const float4*)(g_H + grow * 64 + c8 + 4);
            hres[0]=r0.x;hres[1]=r0.y;hres[2]=r0.z;hres[3]=r0.w;
            hres[4]=r1.x;hres[5]=r1.y;hres[6]=r1.z;hres[7]=r1.w;
        } else {
            #pragma unroll
            for (int u = 0; u < 8; u++) hres[u] = 0.0f;
        }
        float val[8];
        #pragma unroll
        for (int j = 0; j < 4; j++) {
            float2 a = unpack2(acc[i][j]);
            val[2*j]   = fmaxf(a.x + cbv[2*j],   0.0f) + hres[2*j];
            val[2*j+1] = fmaxf(a.y + cbv[2*j+1], 0.0f) + hres[2*j+1];
        }
        float s = 0.0f;
        #pragma unroll
        for (int u = 0; u < 8; u++) s += val[u];
        #pragma unroll
        for (int m = 1; m < 8; m <<= 1) s += __shfl_xor_sync(0xffffffffu, s, m);
        float mu = s * (1.0f / 64.0f);
        float q = 0.0f;
        #pragma unroll
        for (int u = 0; u < 8; u++) { float d = val[u] - mu; q += d * d; }
        #pragma unroll
        for (int m = 1; m < 8; m <<= 1) q += __shfl_xor_sync(0xffffffffu, q, m);
        float rs = rsqrtf(q * (1.0f / 64.0f) + LN_EPS);

        float o[8];
        #pragma unroll
        for (int u = 0; u < 8; u++)
            o[u] = (val[u] - mu) * rs * lgv[u] + lbv[u];

        if (!last) {
            if (grow < n) {
                *(float4*)(g_H + grow * 64 + c8)     = make_float4(o[0], o[1], o[2], o[3]);
                *(float4*)(g_H + grow * 64 + c8 + 4) = make_float4(o[4], o[5], o[6], o[7]);
            }
        } else {
            float4 oa = make_float4(0.f, 0.f, 0.f, 0.f);
            #pragma unroll
            for (int u = 0; u < 8; u++) {
                const float* wr = &sWout[(c8 + u) * 4];
                oa.x += o[u] * wr[0]; oa.y += o[u] * wr[1];
                oa.z += o[u] * wr[2]; oa.w += o[u] * wr[3];
            }
            #pragma unroll
            for (int m = 1; m < 8; m <<= 1) {
                oa.x += __shfl_xor_sync(0xffffffffu, oa.x, m);
                oa.y += __shfl_xor_sync(0xffffffffu, oa.y, m);
                oa.z += __shfl_xor_sync(0xffffffffu, oa.z, m);
                oa.w += __shfl_xor_sync(0xffffffffu, oa.w, m);
            }
            if ((t & 7) == 0 && grow < n) {
                oa.x += sWout[256]; oa.y += sWout[257]; oa.z += sWout[258]; oa.w += sWout[259];
                *(float4*)(out + grow * 4) = oa;
            }
        }
    }
}

// ---------------- launch ----------------
extern "C" void kernel_launch(void* const* d_in, const int* in_sizes, int n_in,
                              void* d_out, int out_size) {
    const float *x = 0, *Win = 0, *bin = 0, *chW = 0, *Wout = 0, *bout = 0;
    const float *p192[3] = {0, 0, 0};
    const int* ei = 0;
    int n192 = 0, e2 = 0, nx = 0;
    for (int i = 0; i < n_in; i++) {
        int sz = in_sizes[i];
        if      (sz == 1600000) { ei = (const int*)d_in[i]; e2 = sz; }
        else if (sz == 800000)  { x = (const float*)d_in[i]; nx = sz; }
        else if (sz == 1024)    Win  = (const float*)d_in[i];
        else if (sz == 64)      bin  = (const float*)d_in[i];
        else if (sz == 36864)   chW  = (const float*)d_in[i];
        else if (sz == 256)     Wout = (const float*)d_in[i];
        else if (sz == 4)       bout = (const float*)d_in[i];
        else if (sz == 192 && n192 < 3) p192[n192++] = (const float*)d_in[i];
    }
    const float* chb = p192[0];
    const float* lng = p192[1];
    const float* lnb = p192[2];
    float* out = (float*)d_out;

    int n = nx / 16;
    int e = e2 / 2;
    const int* src = ei;
    const int* dst = ei + e;

    static cudaStream_t s1 = 0;
    static cudaEvent_t  ev0 = 0, ev1 = 0;
    static int s_init = 0;
    if (!s_init) {
        cudaStreamCreateWithFlags(&s1, cudaStreamNonBlocking);
        cudaEventCreateWithFlags(&ev0, cudaEventDisableTiming);
        cudaEventCreateWithFlags(&ev1, cudaEventDisableTiming);
        cudaFuncSetAttribute(layer_kernel, cudaFuncAttributeMaxDynamicSharedMemorySize,
                             LK_SMEM_BYTES);
        s_init = 1;
    }

    cudaStream_t s0 = 0;
    int ingemm_blocks = (n + 31) / 32;
    int layer_blocks  = (n + 127) / 128;
    int spmm_blocks   = (n * 16 + 255) / 256;
    int scan_blocks   = (n + SCAN_CHUNK - 1) / SCAN_CHUNK;

    // fork: prepA + ingemm concurrent with CSR build (independent inputs)
    cudaEventRecord(ev0, s0);
    cudaStreamWaitEvent(s1, ev0, 0);
    prepA_kernel<<<(3 * 4096 + 255) / 256, 256, 0, s1>>>(chW);
    ingemm_kernel<<<ingemm_blocks, 256, 0, s1>>>(x, Win, bin, n);
    cudaEventRecord(ev1, s1);

    // CSR build (default stream) — counters pre-zeroed (self-cleaning)
    count_kernel<<<(e + 255) / 256, 256, 0, s0>>>(src, dst, e);
    scan_kernel<<<scan_blocks, 1024, 0, s0>>>(n);  // comm-free scan + dinv + re-zero
    scatter_kernel<<<(e + 255) / 256, 256, 0, s0>>>(src, dst, e, n);
    cudaStreamWaitEvent(s0, ev1, 0);

    for (int i = 0; i < 3; i++) {
        spmm_kernel<<<spmm_blocks, 256, 0, s0>>>(0, n);  // T1 = L_hat @ H
        spmm_kernel<<<spmm_blocks, 256, 0, s0>>>(1, n);  // T2 = L_hat @ T1
        layer_kernel<<<layer_blocks, 256, LK_SMEM_BYTES, s0>>>(
            i, chb + i * 64, lng + i * 64, lnb + i * 64,
            Wout, bout, out, (i == 2) ? 1 : 0, n);
    }
}

// round 10
// speedup vs baseline: 2.2592x; 1.0047x over previous
#include <cuda_runtime.h>

#define NMAX 50000
#define EMAX 800000
#define HIDDIM 64
#define LN_EPS 1e-5f
#define SCAN_CHUNK 4096

// ---------------- scratch (device globals; no allocation allowed) ----------------
// Self-cleaning counters: zero at module load; scan_kernel zeroes srcdeg/cursor
// (own chunk), scatter_kernel zeroes rowcnt. Deterministic across graph replays.
__device__ __align__(16) int   g_srcdeg[NMAX];
__device__ __align__(16) int   g_rowcnt[NMAX];
__device__ __align__(16) int   g_cursor[NMAX];
__device__ __align__(16) int   g_rowptr[NMAX + 1];
__device__ __align__(16) float g_dinv[NMAX];
__device__ __align__(16) int2  g_csr[EMAX];              // {src, bitcast(w)} grouped by dst
__device__ __align__(16) float g_H [NMAX * HIDDIM];
__device__ __align__(16) float g_T1[NMAX * HIDDIM];
__device__ __align__(16) float g_T2[NMAX * HIDDIM];
__device__ __align__(16) float g_A [3 * 3 * HIDDIM * HIDDIM];  // folded weights per layer

// ---------------- f32x2 packed-FMA helpers (sm_100+ PTX) ----------------
__device__ __forceinline__ unsigned long long pack2(float a, float b) {
    unsigned long long r;
    asm("mov.b64 %0, {%1, %2};" : "=l"(r) : "f"(a), "f"(b));
    return r;
}
__device__ __forceinline__ unsigned long long ffma2(unsigned long long a,
                                                    unsigned long long b,
                                                    unsigned long long c) {
    unsigned long long d;
    asm("fma.rn.f32x2 %0, %1, %2, %3;" : "=l"(d) : "l"(a), "l"(b), "l"(c));
    return d;
}
__device__ __forceinline__ float2 unpack2(unsigned long long v) {
    float2 f;
    asm("mov.b64 {%0, %1}, %2;" : "=f"(f.x), "=f"(f.y) : "l"(v));
    return f;
}

// ---------------- fused input GEMM + weight folding ----------------
// blocks [0, gemm_blocks): g_H = x @ W_in + b_in
// blocks [gemm_blocks, +48): A0 = W0 - W2, A1 = W1, A2 = 2*W2
__global__ __launch_bounds__(256) void ingemm_prep_kernel(const float* __restrict__ x,
                                                          const float* __restrict__ Win,
                                                          const float* __restrict__ bin,
                                                          const float* __restrict__ chW,
                                                          int gemm_blocks, int n) {
    if (blockIdx.x >= gemm_blocks) {
        int idx = (blockIdx.x - gemm_blocks) * 256 + threadIdx.x;
        if (idx < 3 * 4096) {
            int i = idx >> 12, r = idx & 4095;
            const float* Wi = chW + i * 3 * 4096;
            float w0 = Wi[r], w1 = Wi[4096 + r], w2 = Wi[8192 + r];
            float* Ai = g_A + i * 3 * 4096;
            Ai[r]        = w0 - w2;
            Ai[4096 + r] = w1;
            Ai[8192 + r] = 2.0f * w2;
        }
        return;
    }
    __shared__ float sW[16 * 64];
    __shared__ float xt[16 * 33];
    __shared__ float so[32 * 65];
    int t = threadIdx.x, lane = t & 31, wg = t >> 5;
    int row0 = blockIdx.x * 32;
    for (int idx = t; idx < 1024; idx += 256) sW[idx] = Win[idx];
    for (int idx = t; idx < 512; idx += 256) {
        int r = idx >> 4, k = idx & 15;
        int row = row0 + r;
        xt[k * 33 + r] = (row < n) ? x[row * 16 + k] : 0.0f;
    }
    __syncthreads();
    float acc[8] = {0, 0, 0, 0, 0, 0, 0, 0};
    #pragma unroll
    for (int k = 0; k < 16; k++) {
        float xv = xt[k * 33 + lane];
        float4 w0 = *(const float4*)&sW[k * 64 + wg * 8];
        float4 w1 = *(const float4*)&sW[k * 64 + wg * 8 + 4];
        acc[0] += xv * w0.x; acc[1] += xv * w0.y; acc[2] += xv * w0.z; acc[3] += xv * w0.w;
        acc[4] += xv * w1.x; acc[5] += xv * w1.y; acc[6] += xv * w1.z; acc[7] += xv * w1.w;
    }
    #pragma unroll
    for (int u = 0; u < 8; u++) {
        int j = wg * 8 + u;
        so[lane * 65 + j] = acc[u] + bin[j];
    }
    __syncthreads();
    int r = t >> 3, c = (t & 7) * 8;
    int row = row0 + r;
    if (row < n) {
        float4 v0, v1;
        v0.x = so[r*65+c+0]; v0.y = so[r*65+c+1]; v0.z = so[r*65+c+2]; v0.w = so[r*65+c+3];
        v1.x = so[r*65+c+4]; v1.y = so[r*65+c+5]; v1.z = so[r*65+c+6]; v1.w = so[r*65+c+7];
        *(float4*)(g_H + row * 64 + c)     = v0;
        *(float4*)(g_H + row * 64 + c + 4) = v1;
    }
}

// scalar, 1 edge/thread (measured fastest across rounds)
__global__ void count_kernel(const int* __restrict__ src, const int* __restrict__ dst, int e) {
    int i = blockIdx.x * blockDim.x + threadIdx.x;
    if (i < e) {
        atomicAdd(&g_srcdeg[src[i]], 1);
        atomicAdd(&g_rowcnt[dst[i]], 1);
    }
}

// ---------------- communication-free scan: rowcnt -> rowptr (exclusive) --------
__global__ __launch_bounds__(1024) void scan_kernel(int n) {
#if __CUDA_ARCH__ >= 900
    cudaGridDependencySynchronize();
#endif
    __shared__ int warp_tot[32];
    __shared__ int warp_sum[32];
    __shared__ int s_prev;
    int b = blockIdx.x, t = threadIdx.x, lane = t & 31, wid = t >> 5;
    int i = b * SCAN_CHUNK + t * 4;
    const int4 zero4 = make_int4(0, 0, 0, 0);

    int4 v = zero4;
    bool act = (i + 3) < n;
    if (act) {
        v = *(const int4*)(g_rowcnt + i);
        int4 dg = *(const int4*)(g_srcdeg + i);
        *(int4*)(g_srcdeg + i) = zero4;
        *(int4*)(g_cursor + i) = zero4;
        float4 dv;
        dv.x = (dg.x > 0) ? rsqrtf((float)dg.x) : 0.0f;
        dv.y = (dg.y > 0) ? rsqrtf((float)dg.y) : 0.0f;
        dv.z = (dg.z > 0) ? rsqrtf((float)dg.z) : 0.0f;
        dv.w = (dg.w > 0) ? rsqrtf((float)dg.w) : 0.0f;
        *(float4*)(g_dinv + i) = dv;
    } else {
        for (int q = 0; q < 4; q++) {
            int ii = i + q;
            if (ii < n) {
                ((int*)&v)[q] = g_rowcnt[ii];
                int d = g_srcdeg[ii]; g_srcdeg[ii] = 0;
                g_cursor[ii] = 0;
                g_dinv[ii] = (d > 0) ? rsqrtf((float)d) : 0.0f;
            }
        }
    }

    // prefix over predecessor chunks: direct parallel reduction
    int psum = 0;
    int m = b * SCAN_CHUNK;
    for (int j = t * 4; j < m; j += 4096) {
        int4 c = *(const int4*)(g_rowcnt + j);
        psum += c.x + c.y + c.z + c.w;
    }
    #pragma unroll
    for (int off = 16; off > 0; off >>= 1)
        psum += __shfl_xor_sync(0xffffffffu, psum, off);
    if (lane == 0) warp_sum[wid] = psum;

    int tsum = v.x + v.y + v.z + v.w;
    int x = tsum;
    #pragma unroll
    for (int off = 1; off < 32; off <<= 1) {
        int y = __shfl_up_sync(0xffffffffu, x, off);
        if (lane >= off) x += y;
    }
    if (lane == 31) warp_tot[wid] = x;
    __syncthreads();
    if (wid == 0) {
        int wt = warp_tot[lane];
        #pragma unroll
        for (int off = 1; off < 32; off <<= 1) {
            int y = __shfl_up_sync(0xffffffffu, wt, off);
            if (lane >= off) wt += y;
        }
        warp_tot[lane] = wt;
        int p = warp_sum[lane];
        #pragma unroll
        for (int off = 16; off > 0; off >>= 1)
            p += __shfl_xor_sync(0xffffffffu, p, off);
        if (lane == 0) s_prev = p;
    }
    __syncthreads();
    int wp = (wid > 0) ? warp_tot[wid - 1] : 0;
    int base = s_prev + wp + (x - tsum);

    if (act) {
        int4 rp;
        rp.x = base;
        rp.y = base + v.x;
        rp.z = base + v.x + v.y;
        rp.w = base + v.x + v.y + v.z;
        *(int4*)(g_rowptr + i) = rp;
    } else {
        int c = base;
        for (int q = 0; q < 4; q++) {
            int ii = i + q;
            if (ii < n) { g_rowptr[ii] = c; c += ((int*)&v)[q]; }
        }
    }
    if (b == gridDim.x - 1 && t == 1023)
        g_rowptr[n] = s_prev + warp_tot[31];
}

// scatter + deferred rowcnt re-zero
__global__ void scatter_kernel(const int* __restrict__ src, const int* __restrict__ dst,
                               int e, int n) {
#if __CUDA_ARCH__ >= 900
    cudaGridDependencySynchronize();
#endif
    int i = blockIdx.x * blockDim.x + threadIdx.x;
    if (i < n) g_rowcnt[i] = 0;
    if (i < e) {
        int s = src[i], d = dst[i];
        float w = -g_dinv[s] * g_dinv[d];
        int pos = g_rowptr[d] + atomicAdd(&g_cursor[d], 1);
        g_csr[pos] = make_int2(s, __float_as_int(w));
    }
}

// ---------------- SpMM: Y[dst] = sum_e w * X[src]  (16 threads per row) ----------------
__global__ __launch_bounds__(256) void spmm_kernel(int mode, int n) {
#if __CUDA_ARCH__ >= 900
    cudaGridDependencySynchronize();
#endif
    const float* __restrict__ X = mode ? g_T1 : g_H;
    float* __restrict__ Y       = mode ? g_T2 : g_T1;
    int gid  = blockIdx.x * blockDim.x + threadIdx.x;
    int row  = gid >> 4;
    int lane = gid & 15;
    if (row >= n) return;
    int beg = g_rowptr[row], end = g_rowptr[row + 1];
    float4 a0 = make_float4(0.f, 0.f, 0.f, 0.f);
    float4 a1 = make_float4(0.f, 0.f, 0.f, 0.f);
    int e = beg;
    if ((e & 1) && e < end) {            // align to int4 boundary
        int2 c0 = g_csr[e];
        float4 v0 = *(const float4*)(X + c0.x * HIDDIM + lane * 4);
        float w0 = __int_as_float(c0.y);
        a0.x += w0 * v0.x; a0.y += w0 * v0.y; a0.z += w0 * v0.z; a0.w += w0 * v0.w;
        e++;
    }
    for (; e + 2 <= end; e += 2) {
        int4 c = *(const int4*)(g_csr + e);   // two entries, 16B aligned
        float4 v0 = *(const float4*)(X + c.x * HIDDIM + lane * 4);
        float4 v1 = *(const float4*)(X + c.z * HIDDIM + lane * 4);
        float w0 = __int_as_float(c.y), w1 = __int_as_float(c.w);
        a0.x += w0 * v0.x; a0.y += w0 * v0.y; a0.z += w0 * v0.z; a0.w += w0 * v0.w;
        a1.x += w1 * v1.x; a1.y += w1 * v1.y; a1.z += w1 * v1.z; a1.w += w1 * v1.w;
    }
    if (e < end) {
        int2 c0 = g_csr[e];
        float4 v0 = *(const float4*)(X + c0.x * HIDDIM + lane * 4);
        float w0 = __int_as_float(c0.y);
        a0.x += w0 * v0.x; a0.y += w0 * v0.y; a0.z += w0 * v0.z; a0.w += w0 * v0.w;
    }
    float4 r;
    r.x = a0.x + a1.x; r.y = a0.y + a1.y; r.z = a0.z + a1.z; r.w = a0.w + a1.w;
    *(float4*)(Y + row * HIDDIM + lane * 4) = r;
}

// ---------------- fused layer (128 rows/block, f32x2 FMA, fused out-GEMM on last) ----
// Pass order T1, T2, H(last) so smem tile holds H at the epilogue (residual from smem).
#define LK_HT_STRIDE 129
#define LK_HT_FLOATS (64 * LK_HT_STRIDE)          // 8256
#define LK_SMEM_BYTES ((LK_HT_FLOATS + 4096) * 4) // 49408

__global__ __launch_bounds__(256) void layer_kernel(int layer,
                                                    const float* __restrict__ cb,
                                                    const float* __restrict__ lg,
                                                    const float* __restrict__ lbeta,
                                                    const float* __restrict__ Wout,
                                                    const float* __restrict__ bout,
                                                    float* __restrict__ out,
                                                    int last, int n) {
#if __CUDA_ARCH__ >= 900
    cudaGridDependencySynchronize();
#endif
    extern __shared__ float smem[];
    float* ht = smem;                 // [64][129] transposed tile
    float* sA = smem + LK_HT_FLOATS;  // [64][64] current weight matrix
    __shared__ float sWout[260];

    int t = threadIdx.x;
    int c8 = (t & 7) * 8;             // column group (8 cols)
    int rg = t >> 3;                  // row group (4 rows)
    int row0 = blockIdx.x * 128;
    const float* __restrict__ A = g_A + layer * 12288;

    if (last) {
        sWout[t] = Wout[t];
        if (t < 4) sWout[256 + t] = bout[t];
    }

    unsigned long long acc[4][4];
    #pragma unroll
    for (int i = 0; i < 4; i++)
        #pragma unroll
        for (int j = 0; j < 4; j++) acc[i][j] = pack2(0.0f, 0.0f);

    #pragma unroll
    for (int pass = 0; pass < 3; pass++) {
        // order: T1@A1, T2@A2, H@A0 (H last -> ht holds H at epilogue)
        const float* __restrict__ S  = (pass == 0) ? g_T1 : ((pass == 1) ? g_T2 : g_H);
        const float* __restrict__ Ap = A + ((pass == 0) ? 4096 : ((pass == 1) ? 8192 : 0));
        for (int idx = t; idx < 1024; idx += 256)
            ((float4*)sA)[idx] = ((const float4*)Ap)[idx];
        for (int idx = t; idx < 2048; idx += 256) {
            int r = idx >> 4, k4 = (idx & 15) * 4;
            int grow = row0 + r;
            float4 v = make_float4(0.f, 0.f, 0.f, 0.f);
            if (grow < n) v = *(const float4*)(S + grow * 64 + k4);
            int b = k4 * LK_HT_STRIDE + r;
            ht[b]                    = v.x;
            ht[b + LK_HT_STRIDE]     = v.y;
            ht[b + 2 * LK_HT_STRIDE] = v.z;
            ht[b + 3 * LK_HT_STRIDE] = v.w;
        }
        __syncthreads();
        #pragma unroll 8
        for (int k = 0; k < 64; k++) {
            unsigned long long h2[4];
            #pragma unroll
            for (int i = 0; i < 4; i++) {
                float hv = ht[k * LK_HT_STRIDE + rg * 4 + i];
                h2[i] = pack2(hv, hv);
            }
            float4 wa = *(const float4*)&sA[k * 64 + c8];
            float4 wb = *(const float4*)&sA[k * 64 + c8 + 4];
            unsigned long long w2[4];
            w2[0] = pack2(wa.x, wa.y); w2[1] = pack2(wa.z, wa.w);
            w2[2] = pack2(wb.x, wb.y); w2[3] = pack2(wb.z, wb.w);
            #pragma unroll
            for (int i = 0; i < 4; i++)
                #pragma unroll
                for (int j = 0; j < 4; j++)
                    acc[i][j] = ffma2(h2[i], w2[j], acc[i][j]);
        }
        if (pass < 2) __syncthreads();
    }

    // ---- epilogue: bias + relu + residual (from smem H tile) + layernorm ----
    float cbv[8], lgv[8], lbv[8];
    {
        float4 a0 = *(const float4*)(cb + c8),    a1 = *(const float4*)(cb + c8 + 4);
        float4 g0 = *(const float4*)(lg + c8),    g1 = *(const float4*)(lg + c8 + 4);
        float4 b0 = *(const float4*)(lbeta + c8), b1 = *(const float4*)(lbeta + c8 + 4);
        cbv[0]=a0.x;cbv[1]=a0.y;cbv[2]=a0.z;cbv[3]=a0.w;cbv[4]=a1.x;cbv[5]=a1.y;cbv[6]=a1.z;cbv[7]=a1.w;
        lgv[0]=g0.x;lgv[1]=g0.y;lgv[2]=g0.z;lgv[3]=g0.w;lgv[4]=g1.x;lgv[5]=g1.y;lgv[6]=g1.z;lgv[7]=g1.w;
        lbv[0]=b0.x;lbv[1]=b0.y;lbv[2]=b0.z;lbv[3]=b0.w;lbv[4]=b1.x;lbv[5]=b1.y;lbv[6]=b1.z;lbv[7]=b1.w;
    }

    #pragma unroll
    for (int i = 0; i < 4; i++) {
        int grow = row0 + rg * 4 + i;
        float val[8];
        #pragma unroll
        for (int j = 0; j < 4; j++) {
            float2 a = unpack2(acc[i][j]);
            float hr0 = ht[(c8 + 2*j)     * LK_HT_STRIDE + rg * 4 + i];
            float hr1 = ht[(c8 + 2*j + 1) * LK_HT_STRIDE + rg * 4 + i];
            val[2*j]   = fmaxf(a.x + cbv[2*j],   0.0f) + hr0;
            val[2*j+1] = fmaxf(a.y + cbv[2*j+1], 0.0f) + hr1;
        }
        float s = 0.0f;
        #pragma unroll
        for (int u = 0; u < 8; u++) s += val[u];
        #pragma unroll
        for (int m = 1; m < 8; m <<= 1) s += __shfl_xor_sync(0xffffffffu, s, m);
        float mu = s * (1.0f / 64.0f);
        float q = 0.0f;
        #pragma unroll
        for (int u = 0; u < 8; u++) { float d = val[u] - mu; q += d * d; }
        #pragma unroll
        for (int m = 1; m < 8; m <<= 1) q += __shfl_xor_sync(0xffffffffu, q, m);
        float rs = rsqrtf(q * (1.0f / 64.0f) + LN_EPS);

        float o[8];
        #pragma unroll
        for (int u = 0; u < 8; u++)
            o[u] = (val[u] - mu) * rs * lgv[u] + lbv[u];

        if (!last) {
            if (grow < n) {
                *(float4*)(g_H + grow * 64 + c8)     = make_float4(o[0], o[1], o[2], o[3]);
                *(float4*)(g_H + grow * 64 + c8 + 4) = make_float4(o[4], o[5], o[6], o[7]);
            }
        } else {
            float4 oa = make_float4(0.f, 0.f, 0.f, 0.f);
            #pragma unroll
            for (int u = 0; u < 8; u++) {
                const float* wr = &sWout[(c8 + u) * 4];
                oa.x += o[u] * wr[0]; oa.y += o[u] * wr[1];
                oa.z += o[u] * wr[2]; oa.w += o[u] * wr[3];
            }
            #pragma unroll
            for (int m = 1; m < 8; m <<= 1) {
                oa.x += __shfl_xor_sync(0xffffffffu, oa.x, m);
                oa.y += __shfl_xor_sync(0xffffffffu, oa.y, m);
                oa.z += __shfl_xor_sync(0xffffffffu, oa.z, m);
                oa.w += __shfl_xor_sync(0xffffffffu, oa.w, m);
            }
            if ((t & 7) == 0 && grow < n) {
                oa.x += sWout[256]; oa.y += sWout[257]; oa.z += sWout[258]; oa.w += sWout[259];
                *(float4*)(out + grow * 4) = oa;
            }
        }
    }
}

// ---------------- PDL launch helper ----------------
template <typename F, typename... Args>
static inline void launch_pdl(F kernel, dim3 grid, dim3 block, size_t smem,
                              cudaStream_t stream, Args... args) {
    cudaLaunchConfig_t cfg = {};
    cfg.gridDim = grid; cfg.blockDim = block;
    cfg.dynamicSmemBytes = smem; cfg.stream = stream;
    cudaLaunchAttribute attr[1];
    attr[0].id = cudaLaunchAttributeProgrammaticStreamSerialization;
    attr[0].val.programmaticStreamSerializationAllowed = 1;
    cfg.attrs = attr; cfg.numAttrs = 1;
    cudaLaunchKernelEx(&cfg, kernel, args...);
}

// ---------------- launch ----------------
extern "C" void kernel_launch(void* const* d_in, const int* in_sizes, int n_in,
                              void* d_out, int out_size) {
    const float *x = 0, *Win = 0, *bin = 0, *chW = 0, *Wout = 0, *bout = 0;
    const float *p192[3] = {0, 0, 0};
    const int* ei = 0;
    int n192 = 0, e2 = 0, nx = 0;
    for (int i = 0; i < n_in; i++) {
        int sz = in_sizes[i];
        if      (sz == 1600000) { ei = (const int*)d_in[i]; e2 = sz; }
        else if (sz == 800000)  { x = (const float*)d_in[i]; nx = sz; }
        else if (sz == 1024)    Win  = (const float*)d_in[i];
        else if (sz == 64)      bin  = (const float*)d_in[i];
        else if (sz == 36864)   chW  = (const float*)d_in[i];
        else if (sz == 256)     Wout = (const float*)d_in[i];
        else if (sz == 4)       bout = (const float*)d_in[i];
        else if (sz == 192 && n192 < 3) p192[n192++] = (const float*)d_in[i];
    }
    const float* chb = p192[0];
    const float* lng = p192[1];
    const float* lnb = p192[2];
    float* out = (float*)d_out;

    int n = nx / 16;
    int e = e2 / 2;
    const int* src = ei;
    const int* dst = ei + e;

    static cudaStream_t s1 = 0;
    static cudaEvent_t  ev0 = 0, ev1 = 0;
    static int s_init = 0;
    if (!s_init) {
        cudaStreamCreateWithFlags(&s1, cudaStreamNonBlocking);
        cudaEventCreateWithFlags(&ev0, cudaEventDisableTiming);
        cudaEventCreateWithFlags(&ev1, cudaEventDisableTiming);
        cudaFuncSetAttribute(layer_kernel, cudaFuncAttributeMaxDynamicSharedMemorySize,
                             LK_SMEM_BYTES);
        s_init = 1;
    }

    cudaStream_t s0 = 0;
    int gemm_blocks   = (n + 31) / 32;
    int layer_blocks  = (n + 127) / 128;
    int spmm_blocks   = (n * 16 + 255) / 256;
    int scan_blocks   = (n + SCAN_CHUNK - 1) / SCAN_CHUNK;

    // fork: ingemm+prepA (merged) concurrent with CSR build (independent data)
    cudaEventRecord(ev0, s0);
    cudaStreamWaitEvent(s1, ev0, 0);
    ingemm_prep_kernel<<<gemm_blocks + 48, 256, 0, s1>>>(x, Win, bin, chW, gemm_blocks, n);
    cudaEventRecord(ev1, s1);

    // CSR build on s0 with PDL between dependent nodes
    count_kernel<<<(e + 255) / 256, 256, 0, s0>>>(src, dst, e);
    launch_pdl(scan_kernel, dim3(scan_blocks), dim3(1024), 0, s0, n);
    launch_pdl(scatter_kernel, dim3((e + 255) / 256), dim3(256), 0, s0, src, dst, e, n);
    cudaStreamWaitEvent(s0, ev1, 0);

    for (int i = 0; i < 3; i++) {
        if (i == 0) {
            // first spmm follows an event-wait join: launch normally
            spmm_kernel<<<spmm_blocks, 256, 0, s0>>>(0, n);
        } else {
            launch_pdl(spmm_kernel, dim3(spmm_blocks), dim3(256), 0, s0, 0, n);
        }
        launch_pdl(spmm_kernel, dim3(spmm_blocks), dim3(256), 0, s0, 1, n);
        launch_pdl(layer_kernel, dim3(layer_blocks), dim3(256), (size_t)LK_SMEM_BYTES, s0,
                   i, chb + i * 64, lng + i * 64, lnb + i * 64,
                   Wout, bout, out, (i == 2) ? 1 : 0, n);
    }
}

// round 11
// speedup vs baseline: 2.3482x; 1.0394x over previous
#include <cuda_runtime.h>
#include <cuda_fp16.h>

#define NMAX 50000
#define EMAX 800000
#define HIDDIM 64
#define LN_EPS 1e-5f
#define SCAN_CHUNK 4096

// ---------------- scratch (device globals; no allocation allowed) ----------------
// Self-cleaning counters: zero at module load; scan_kernel zeroes srcdeg/cursor
// (own chunk), scatter_kernel zeroes rowcnt. Deterministic across graph replays.
__device__ __align__(16) int   g_srcdeg[NMAX];
__device__ __align__(16) int   g_rowcnt[NMAX];
__device__ __align__(16) int   g_cursor[NMAX];
__device__ __align__(16) int   g_rowptr[NMAX + 1];
__device__ __align__(16) float g_dinv[NMAX];
__device__ __align__(16) int2  g_csr[EMAX];              // {src, bitcast(w)} grouped by dst
__device__ __align__(16) float g_H [NMAX * HIDDIM];
__device__ __align__(16) float g_T1[NMAX * HIDDIM];
__device__ __align__(16) float g_T2[NMAX * HIDDIM];
__device__ __align__(16) __half2 g_Hh [NMAX * 32];       // fp16 copy of H  (spmm gather)
__device__ __align__(16) __half2 g_T1h[NMAX * 32];       // fp16 copy of T1 (spmm gather)
__device__ __align__(16) float g_A [3 * 3 * HIDDIM * HIDDIM];  // folded weights per layer

// ---------------- f32x2 packed-FMA helpers (sm_100+ PTX) ----------------
__device__ __forceinline__ unsigned long long pack2(float a, float b) {
    unsigned long long r;
    asm("mov.b64 %0, {%1, %2};" : "=l"(r) : "f"(a), "f"(b));
    return r;
}
__device__ __forceinline__ unsigned long long ffma2(unsigned long long a,
                                                    unsigned long long b,
                                                    unsigned long long c) {
    unsigned long long d;
    asm("fma.rn.f32x2 %0, %1, %2, %3;" : "=l"(d) : "l"(a), "l"(b), "l"(c));
    return d;
}
__device__ __forceinline__ float2 unpack2(unsigned long long v) {
    float2 f;
    asm("mov.b64 {%0, %1}, %2;" : "=f"(f.x), "=f"(f.y) : "l"(v));
    return f;
}

// pack 8 floats -> uint4 of 8 halves
__device__ __forceinline__ uint4 pack_half8(const float* o) {
    union { __half2 h[4]; uint4 u; } p;
    p.h[0] = __float22half2_rn(make_float2(o[0], o[1]));
    p.h[1] = __float22half2_rn(make_float2(o[2], o[3]));
    p.h[2] = __float22half2_rn(make_float2(o[4], o[5]));
    p.h[3] = __float22half2_rn(make_float2(o[6], o[7]));
    return p.u;
}

// ---------------- fused input GEMM + weight folding ----------------
__global__ __launch_bounds__(256) void ingemm_prep_kernel(const float* __restrict__ x,
                                                          const float* __restrict__ Win,
                                                          const float* __restrict__ bin,
                                                          const float* __restrict__ chW,
                                                          int gemm_blocks, int n) {
    if (blockIdx.x >= gemm_blocks) {
        int idx = (blockIdx.x - gemm_blocks) * 256 + threadIdx.x;
        if (idx < 3 * 4096) {
            int i = idx >> 12, r = idx & 4095;
            const float* Wi = chW + i * 3 * 4096;
            float w0 = Wi[r], w1 = Wi[4096 + r], w2 = Wi[8192 + r];
            float* Ai = g_A + i * 3 * 4096;
            Ai[r]        = w0 - w2;
            Ai[4096 + r] = w1;
            Ai[8192 + r] = 2.0f * w2;
        }
        return;
    }
    __shared__ float sW[16 * 64];
    __shared__ float xt[16 * 33];
    __shared__ float so[32 * 65];
    int t = threadIdx.x, lane = t & 31, wg = t >> 5;
    int row0 = blockIdx.x * 32;
    for (int idx = t; idx < 1024; idx += 256) sW[idx] = Win[idx];
    for (int idx = t; idx < 512; idx += 256) {
        int r = idx >> 4, k = idx & 15;
        int row = row0 + r;
        xt[k * 33 + r] = (row < n) ? x[row * 16 + k] : 0.0f;
    }
    __syncthreads();
    float acc[8] = {0, 0, 0, 0, 0, 0, 0, 0};
    #pragma unroll
    for (int k = 0; k < 16; k++) {
        float xv = xt[k * 33 + lane];
        float4 w0 = *(const float4*)&sW[k * 64 + wg * 8];
        float4 w1 = *(const float4*)&sW[k * 64 + wg * 8 + 4];
        acc[0] += xv * w0.x; acc[1] += xv * w0.y; acc[2] += xv * w0.z; acc[3] += xv * w0.w;
        acc[4] += xv * w1.x; acc[5] += xv * w1.y; acc[6] += xv * w1.z; acc[7] += xv * w1.w;
    }
    #pragma unroll
    for (int u = 0; u < 8; u++) {
        int j = wg * 8 + u;
        so[lane * 65 + j] = acc[u] + bin[j];
    }
    __syncthreads();
    int r = t >> 3, c = (t & 7) * 8;
    int row = row0 + r;
    if (row < n) {
        float v[8];
        #pragma unroll
        for (int u = 0; u < 8; u++) v[u] = so[r * 65 + c + u];
        *(float4*)(g_H + row * 64 + c)     = make_float4(v[0], v[1], v[2], v[3]);
        *(float4*)(g_H + row * 64 + c + 4) = make_float4(v[4], v[5], v[6], v[7]);
        *(uint4*)(g_Hh + row * 32 + c / 2) = pack_half8(v);
    }
}

// scalar, 1 edge/thread (measured fastest across rounds)
__global__ void count_kernel(const int* __restrict__ src, const int* __restrict__ dst, int e) {
    int i = blockIdx.x * blockDim.x + threadIdx.x;
    if (i < e) {
        atomicAdd(&g_srcdeg[src[i]], 1);
        atomicAdd(&g_rowcnt[dst[i]], 1);
    }
}

// ---------------- communication-free scan: rowcnt -> rowptr (exclusive) --------
__global__ __launch_bounds__(1024) void scan_kernel(int n) {
#if __CUDA_ARCH__ >= 900
    cudaGridDependencySynchronize();
#endif
    __shared__ int warp_tot[32];
    __shared__ int warp_sum[32];
    __shared__ int s_prev;
    int b = blockIdx.x, t = threadIdx.x, lane = t & 31, wid = t >> 5;
    int i = b * SCAN_CHUNK + t * 4;
    const int4 zero4 = make_int4(0, 0, 0, 0);

    int4 v = zero4;
    bool act = (i + 3) < n;
    if (act) {
        v = *(const int4*)(g_rowcnt + i);
        int4 dg = *(const int4*)(g_srcdeg + i);
        *(int4*)(g_srcdeg + i) = zero4;
        *(int4*)(g_cursor + i) = zero4;
        float4 dv;
        dv.x = (dg.x > 0) ? rsqrtf((float)dg.x) : 0.0f;
        dv.y = (dg.y > 0) ? rsqrtf((float)dg.y) : 0.0f;
        dv.z = (dg.z > 0) ? rsqrtf((float)dg.z) : 0.0f;
        dv.w = (dg.w > 0) ? rsqrtf((float)dg.w) : 0.0f;
        *(float4*)(g_dinv + i) = dv;
    } else {
        for (int q = 0; q < 4; q++) {
            int ii = i + q;
            if (ii < n) {
                ((int*)&v)[q] = g_rowcnt[ii];
                int d = g_srcdeg[ii]; g_srcdeg[ii] = 0;
                g_cursor[ii] = 0;
                g_dinv[ii] = (d > 0) ? rsqrtf((float)d) : 0.0f;
            }
        }
    }

    int psum = 0;
    int m = b * SCAN_CHUNK;
    for (int j = t * 4; j < m; j += 4096) {
        int4 c = *(const int4*)(g_rowcnt + j);
        psum += c.x + c.y + c.z + c.w;
    }
    #pragma unroll
    for (int off = 16; off > 0; off >>= 1)
        psum += __shfl_xor_sync(0xffffffffu, psum, off);
    if (lane == 0) warp_sum[wid] = psum;

    int tsum = v.x + v.y + v.z + v.w;
    int x = tsum;
    #pragma unroll
    for (int off = 1; off < 32; off <<= 1) {
        int y = __shfl_up_sync(0xffffffffu, x, off);
        if (lane >= off) x += y;
    }
    if (lane == 31) warp_tot[wid] = x;
    __syncthreads();
    if (wid == 0) {
        int wt = warp_tot[lane];
        #pragma unroll
        for (int off = 1; off < 32; off <<= 1) {
            int y = __shfl_up_sync(0xffffffffu, wt, off);
            if (lane >= off) wt += y;
        }
        warp_tot[lane] = wt;
        int p = warp_sum[lane];
        #pragma unroll
        for (int off = 16; off > 0; off >>= 1)
            p += __shfl_xor_sync(0xffffffffu, p, off);
        if (lane == 0) s_prev = p;
    }
    __syncthreads();
    int wp = (wid > 0) ? warp_tot[wid - 1] : 0;
    int base = s_prev + wp + (x - tsum);

    if (act) {
        int4 rp;
        rp.x = base;
        rp.y = base + v.x;
        rp.z = base + v.x + v.y;
        rp.w = base + v.x + v.y + v.z;
        *(int4*)(g_rowptr + i) = rp;
    } else {
        int c = base;
        for (int q = 0; q < 4; q++) {
            int ii = i + q;
            if (ii < n) { g_rowptr[ii] = c; c += ((int*)&v)[q]; }
        }
    }
    if (b == gridDim.x - 1 && t == 1023)
        g_rowptr[n] = s_prev + warp_tot[31];
}

// scatter + deferred rowcnt re-zero
__global__ void scatter_kernel(const int* __restrict__ src, const int* __restrict__ dst,
                               int e, int n) {
#if __CUDA_ARCH__ >= 900
    cudaGridDependencySynchronize();
#endif
    int i = blockIdx.x * blockDim.x + threadIdx.x;
    if (i < n) g_rowcnt[i] = 0;
    if (i < e) {
        int s = src[i], d = dst[i];
        float w = -g_dinv[s] * g_dinv[d];
        int pos = g_rowptr[d] + atomicAdd(&g_cursor[d], 1);
        g_csr[pos] = make_int2(s, __float_as_int(w));
    }
}

// ---------------- SpMM with fp16 gather, fp32 accumulate -----------------------
// mode 0: gather g_Hh  -> T1 (fp32) + g_T1h (fp16)
// mode 1: gather g_T1h -> T2 (fp32)
__global__ __launch_bounds__(256) void spmm_kernel(int mode, int n) {
#if __CUDA_ARCH__ >= 900
    cudaGridDependencySynchronize();
#endif
    const __half2* __restrict__ X = mode ? g_T1h : g_Hh;
    float* __restrict__ Y         = mode ? g_T2  : g_T1;
    int gid  = blockIdx.x * blockDim.x + threadIdx.x;
    int row  = gid >> 4;
    int lane = gid & 15;
    if (row >= n) return;
    int beg = g_rowptr[row], end = g_rowptr[row + 1];
    float4 a0 = make_float4(0.f, 0.f, 0.f, 0.f);
    float4 a1 = make_float4(0.f, 0.f, 0.f, 0.f);
    int e = beg;
    if ((e & 1) && e < end) {
        int2 c0 = g_csr[e];
        uint2 hh = *(const uint2*)(X + c0.x * 32 + lane * 2);
        float2 f0 = __half22float2(*(const __half2*)&hh.x);
        float2 f1 = __half22float2(*(const __half2*)&hh.y);
        float w0 = __int_as_float(c0.y);
        a0.x += w0 * f0.x; a0.y += w0 * f0.y; a0.z += w0 * f1.x; a0.w += w0 * f1.y;
        e++;
    }
    for (; e + 2 <= end; e += 2) {
        int4 c = *(const int4*)(g_csr + e);
        uint2 h0 = *(const uint2*)(X + c.x * 32 + lane * 2);
        uint2 h1 = *(const uint2*)(X + c.z * 32 + lane * 2);
        float2 f00 = __half22float2(*(const __half2*)&h0.x);
        float2 f01 = __half22float2(*(const __half2*)&h0.y);
        float2 f10 = __half22float2(*(const __half2*)&h1.x);
        float2 f11 = __half22float2(*(const __half2*)&h1.y);
        float w0 = __int_as_float(c.y), w1 = __int_as_float(c.w);
        a0.x += w0 * f00.x; a0.y += w0 * f00.y; a0.z += w0 * f01.x; a0.w += w0 * f01.y;
        a1.x += w1 * f10.x; a1.y += w1 * f10.y; a1.z += w1 * f11.x; a1.w += w1 * f11.y;
    }
    if (e < end) {
        int2 c0 = g_csr[e];
        uint2 hh = *(const uint2*)(X + c0.x * 32 + lane * 2);
        float2 f0 = __half22float2(*(const __half2*)&hh.x);
        float2 f1 = __half22float2(*(const __half2*)&hh.y);
        float w0 = __int_as_float(c0.y);
        a0.x += w0 * f0.x; a0.y += w0 * f0.y; a0.z += w0 * f1.x; a0.w += w0 * f1.y;
    }
    float4 r;
    r.x = a0.x + a1.x; r.y = a0.y + a1.y; r.z = a0.z + a1.z; r.w = a0.w + a1.w;
    *(float4*)(Y + row * HIDDIM + lane * 4) = r;
    if (!mode) {
        union { __half2 h[2]; uint2 u; } p;
        p.h[0] = __float22half2_rn(make_float2(r.x, r.y));
        p.h[1] = __float22half2_rn(make_float2(r.z, r.w));
        *(uint2*)(g_T1h + row * 32 + lane * 2) = p.u;
    }
}

// ---------------- fused layer (128 rows/block, f32x2 FMA, fused out-GEMM on last) ----
// Pass order T1, T2, H(last) so smem tile holds H at the epilogue (residual from smem).
#define LK_HT_STRIDE 129
#define LK_HT_FLOATS (64 * LK_HT_STRIDE)          // 8256
#define LK_SMEM_BYTES ((LK_HT_FLOATS + 4096) * 4) // 49408

__global__ __launch_bounds__(256) void layer_kernel(int layer,
                                                    const float* __restrict__ cb,
                                                    const float* __restrict__ lg,
                                                    const float* __restrict__ lbeta,
                                                    const float* __restrict__ Wout,
                                                    const float* __restrict__ bout,
                                                    float* __restrict__ out,
                                                    int last, int n) {
#if __CUDA_ARCH__ >= 900
    cudaGridDependencySynchronize();
#endif
    extern __shared__ float smem[];
    float* ht = smem;                 // [64][129] transposed tile
    float* sA = smem + LK_HT_FLOATS;  // [64][64] current weight matrix
    __shared__ float sWout[260];

    int t = threadIdx.x;
    int c8 = (t & 7) * 8;
    int rg = t >> 3;
    int row0 = blockIdx.x * 128;
    const float* __restrict__ A = g_A + layer * 12288;

    if (last) {
        sWout[t] = Wout[t];
        if (t < 4) sWout[256 + t] = bout[t];
    }

    unsigned long long acc[4][4];
    #pragma unroll
    for (int i = 0; i < 4; i++)
        #pragma unroll
        for (int j = 0; j < 4; j++) acc[i][j] = pack2(0.0f, 0.0f);

    #pragma unroll
    for (int pass = 0; pass < 3; pass++) {
        const float* __restrict__ S  = (pass == 0) ? g_T1 : ((pass == 1) ? g_T2 : g_H);
        const float* __restrict__ Ap = A + ((pass == 0) ? 4096 : ((pass == 1) ? 8192 : 0));
        for (int idx = t; idx < 1024; idx += 256)
            ((float4*)sA)[idx] = ((const float4*)Ap)[idx];
        for (int idx = t; idx < 2048; idx += 256) {
            int r = idx >> 4, k4 = (idx & 15) * 4;
            int grow = row0 + r;
            float4 v = make_float4(0.f, 0.f, 0.f, 0.f);
            if (grow < n) v = *(const float4*)(S + grow * 64 + k4);
            int b = k4 * LK_HT_STRIDE + r;
            ht[b]                    = v.x;
            ht[b + LK_HT_STRIDE]     = v.y;
            ht[b + 2 * LK_HT_STRIDE] = v.z;
            ht[b + 3 * LK_HT_STRIDE] = v.w;
        }
        __syncthreads();
        #pragma unroll 8
        for (int k = 0; k < 64; k++) {
            unsigned long long h2[4];
            #pragma unroll
            for (int i = 0; i < 4; i++) {
                float hv = ht[k * LK_HT_STRIDE + rg * 4 + i];
                h2[i] = pack2(hv, hv);
            }
            float4 wa = *(const float4*)&sA[k * 64 + c8];
            float4 wb = *(const float4*)&sA[k * 64 + c8 + 4];
            unsigned long long w2[4];
            w2[0] = pack2(wa.x, wa.y); w2[1] = pack2(wa.z, wa.w);
            w2[2] = pack2(wb.x, wb.y); w2[3] = pack2(wb.z, wb.w);
            #pragma unroll
            for (int i = 0; i < 4; i++)
                #pragma unroll
                for (int j = 0; j < 4; j++)
                    acc[i][j] = ffma2(h2[i], w2[j], acc[i][j]);
        }
        if (pass < 2) __syncthreads();
    }

    float cbv[8], lgv[8], lbv[8];
    {
        float4 a0 = *(const float4*)(cb + c8),    a1 = *(const float4*)(cb + c8 + 4);
        float4 g0 = *(const float4*)(lg + c8),    g1 = *(const float4*)(lg + c8 + 4);
        float4 b0 = *(const float4*)(lbeta + c8), b1 = *(const float4*)(lbeta + c8 + 4);
        cbv[0]=a0.x;cbv[1]=a0.y;cbv[2]=a0.z;cbv[3]=a0.w;cbv[4]=a1.x;cbv[5]=a1.y;cbv[6]=a1.z;cbv[7]=a1.w;
        lgv[0]=g0.x;lgv[1]=g0.y;lgv[2]=g0.z;lgv[3]=g0.w;lgv[4]=g1.x;lgv[5]=g1.y;lgv[6]=g1.z;lgv[7]=g1.w;
        lbv[0]=b0.x;lbv[1]=b0.y;lbv[2]=b0.z;lbv[3]=b0.w;lbv[4]=b1.x;lbv[5]=b1.y;lbv[6]=b1.z;lbv[7]=b1.w;
    }

    #pragma unroll
    for (int i = 0; i < 4; i++) {
        int grow = row0 + rg * 4 + i;
        float val[8];
        #pragma unroll
        for (int j = 0; j < 4; j++) {
            float2 a = unpack2(acc[i][j]);
            float hr0 = ht[(c8 + 2*j)     * LK_HT_STRIDE + rg * 4 + i];
            float hr1 = ht[(c8 + 2*j + 1) * LK_HT_STRIDE + rg * 4 + i];
            val[2*j]   = fmaxf(a.x + cbv[2*j],   0.0f) + hr0;
            val[2*j+1] = fmaxf(a.y + cbv[2*j+1], 0.0f) + hr1;
        }
        float s = 0.0f;
        #pragma unroll
        for (int u = 0; u < 8; u++) s += val[u];
        #pragma unroll
        for (int m = 1; m < 8; m <<= 1) s += __shfl_xor_sync(0xffffffffu, s, m);
        float mu = s * (1.0f / 64.0f);
        float q = 0.0f;
        #pragma unroll
        for (int u = 0; u < 8; u++) { float d = val[u] - mu; q += d * d; }
        #pragma unroll
        for (int m = 1; m < 8; m <<= 1) q += __shfl_xor_sync(0xffffffffu, q, m);
        float rs = rsqrtf(q * (1.0f / 64.0f) + LN_EPS);

        float o[8];
        #pragma unroll
        for (int u = 0; u < 8; u++)
            o[u] = (val[u] - mu) * rs * lgv[u] + lbv[u];

        if (!last) {
            if (grow < n) {
                *(float4*)(g_H + grow * 64 + c8)     = make_float4(o[0], o[1], o[2], o[3]);
                *(float4*)(g_H + grow * 64 + c8 + 4) = make_float4(o[4], o[5], o[6], o[7]);
                *(uint4*)(g_Hh + grow * 32 + c8 / 2) = pack_half8(o);
            }
        } else {
            float4 oa = make_float4(0.f, 0.f, 0.f, 0.f);
            #pragma unroll
            for (int u = 0; u < 8; u++) {
                const float* wr = &sWout[(c8 + u) * 4];
                oa.x += o[u] * wr[0]; oa.y += o[u] * wr[1];
                oa.z += o[u] * wr[2]; oa.w += o[u] * wr[3];
            }
            #pragma unroll
            for (int m = 1; m < 8; m <<= 1) {
                oa.x += __shfl_xor_sync(0xffffffffu, oa.x, m);
                oa.y += __shfl_xor_sync(0xffffffffu, oa.y, m);
                oa.z += __shfl_xor_sync(0xffffffffu, oa.z, m);
                oa.w += __shfl_xor_sync(0xffffffffu, oa.w, m);
            }
            if ((t & 7) == 0 && grow < n) {
                oa.x += sWout[256]; oa.y += sWout[257]; oa.z += sWout[258]; oa.w += sWout[259];
                *(float4*)(out + grow * 4) = oa;
            }
        }
    }
}

// ---------------- PDL launch helper ----------------
template <typename F, typename... Args>
static inline void launch_pdl(F kernel, dim3 grid, dim3 block, size_t smem,
                              cudaStream_t stream, Args... args) {
    cudaLaunchConfig_t cfg = {};
    cfg.gridDim = grid; cfg.blockDim = block;
    cfg.dynamicSmemBytes = smem; cfg.stream = stream;
    cudaLaunchAttribute attr[1];
    attr[0].id = cudaLaunchAttributeProgrammaticStreamSerialization;
    attr[0].val.programmaticStreamSerializationAllowed = 1;
    cfg.attrs = attr; cfg.numAttrs = 1;
    cudaLaunchKernelEx(&cfg, kernel, args...);
}

// ---------------- launch ----------------
extern "C" void kernel_launch(void* const* d_in, const int* in_sizes, int n_in,
                              void* d_out, int out_size) {
    const float *x = 0, *Win = 0, *bin = 0, *chW = 0, *Wout = 0, *bout = 0;
    const float *p192[3] = {0, 0, 0};
    const int* ei = 0;
    int n192 = 0, e2 = 0, nx = 0;
    for (int i = 0; i < n_in; i++) {
        int sz = in_sizes[i];
        if      (sz == 1600000) { ei = (const int*)d_in[i]; e2 = sz; }
        else if (sz == 800000)  { x = (const float*)d_in[i]; nx = sz; }
        else if (sz == 1024)    Win  = (const float*)d_in[i];
        else if (sz == 64)      bin  = (const float*)d_in[i];
        else if (sz == 36864)   chW  = (const float*)d_in[i];
        else if (sz == 256)     Wout = (const float*)d_in[i];
        else if (sz == 4)       bout = (const float*)d_in[i];
        else if (sz == 192 && n192 < 3) p192[n192++] = (const float*)d_in[i];
    }
    const float* chb = p192[0];
    const float* lng = p192[1];
    const float* lnb = p192[2];
    float* out = (float*)d_out;

    int n = nx / 16;
    int e = e2 / 2;
    const int* src = ei;
    const int* dst = ei + e;

    static cudaStream_t s1 = 0;
    static cudaEvent_t  ev0 = 0, ev1 = 0;
    static int s_init = 0;
    if (!s_init) {
        cudaStreamCreateWithFlags(&s1, cudaStreamNonBlocking);
        cudaEventCreateWithFlags(&ev0, cudaEventDisableTiming);
        cudaEventCreateWithFlags(&ev1, cudaEventDisableTiming);
        cudaFuncSetAttribute(layer_kernel, cudaFuncAttributeMaxDynamicSharedMemorySize,
                             LK_SMEM_BYTES);
        s_init = 1;
    }

    cudaStream_t s0 = 0;
    int gemm_blocks   = (n + 31) / 32;
    int layer_blocks  = (n + 127) / 128;
    int spmm_blocks   = (n * 16 + 255) / 256;
    int scan_blocks   = (n + SCAN_CHUNK - 1) / SCAN_CHUNK;

    // fork: ingemm+prepA (merged) concurrent with CSR build (independent data)
    cudaEventRecord(ev0, s0);
    cudaStreamWaitEvent(s1, ev0, 0);
    ingemm_prep_kernel<<<gemm_blocks + 48, 256, 0, s1>>>(x, Win, bin, chW, gemm_blocks, n);
    cudaEventRecord(ev1, s1);

    // CSR build on s0 with PDL between dependent nodes
    count_kernel<<<(e + 255) / 256, 256, 0, s0>>>(src, dst, e);
    launch_pdl(scan_kernel, dim3(scan_blocks), dim3(1024), 0, s0, n);
    launch_pdl(scatter_kernel, dim3((e + 255) / 256), dim3(256), 0, s0, src, dst, e, n);
    cudaStreamWaitEvent(s0, ev1, 0);

    for (int i = 0; i < 3; i++) {
        if (i == 0) {
            spmm_kernel<<<spmm_blocks, 256, 0, s0>>>(0, n);
        } else {
            launch_pdl(spmm_kernel, dim3(spmm_blocks), dim3(256), 0, s0, 0, n);
        }
        launch_pdl(spmm_kernel, dim3(spmm_blocks), dim3(256), 0, s0, 1, n);
        launch_pdl(layer_kernel, dim3(layer_blocks), dim3(256), (size_t)LK_SMEM_BYTES, s0,
                   i, chb + i * 64, lng + i * 64, lnb + i * 64,
                   Wout, bout, out, (i == 2) ? 1 : 0, n);
    }
}